// round 11
// baseline (speedup 1.0000x reference)
#include <cuda_runtime.h>
#include <cuda_fp16.h>
#include <cstdint>
#include <math.h>
typedef long long LL;

constexpr int Bb=4, Ss=4096, Dm=2048, DFF=8192, Hh=16, HKV=8, DH=128, Rr=64, KD=64, Ff=128;
constexpr int Mtok=Bb*Ss;

__device__ __forceinline__ uint32_t smem_u32(const void* p){uint32_t a;asm("{ .reg .u64 t; cvta.to.shared.u64 t, %1; cvt.u32.u64 %0, t; }":"=r"(a):"l"(p));return a;}
#define SW128(o) ((o) ^ (((o) >> 3) & 0x70))
#define CPA16(dst,src) asm volatile("cp.async.cg.shared.global [%0], [%1], 16;"::"r"(dst),"l"(src):"memory")
#define CPCOMMIT() asm volatile("cp.async.commit_group;":::"memory")
#define CPWAIT(n) asm volatile("cp.async.wait_group %0;"::"n"(n):"memory")
__device__ __forceinline__ void ldsm4(uint32_t* r, uint32_t a){
    asm volatile("ldmatrix.sync.aligned.m8n8.x4.shared.b16 {%0,%1,%2,%3}, [%4];"
        :"=r"(r[0]),"=r"(r[1]),"=r"(r[2]),"=r"(r[3]):"r"(a));}
#define MMA(d,a,b) asm volatile("mma.sync.aligned.m16n8k16.row.col.f32.f16.f16.f32 {%0,%1,%2,%3},{%4,%5,%6,%7},{%8,%9},{%0,%1,%2,%3};" \
  :"+f"((d)[0]),"+f"((d)[1]),"+f"((d)[2]),"+f"((d)[3]) \
  :"r"((a)[0]),"r"((a)[1]),"r"((a)[2]),"r"((a)[3]),"r"((b)[0]),"r"((b)[1]))

__device__ __align__(16) __half g_xh[(LL)Mtok*Dm];
__device__ __align__(16) __half g_xl[(LL)Mtok*Dm];
__device__ __align__(16) __half g_cqh[(LL)Mtok*Rr];
__device__ __align__(16) __half g_cql[(LL)Mtok*Rr];
__device__ __align__(16) __half g_ckvh[(LL)Mtok*Rr];
__device__ __align__(16) __half g_ckvl[(LL)Mtok*Rr];
__device__ __align__(16) float g_q[(LL)Mtok*Dm];
__device__ __align__(16) float g_k[(LL)Mtok*HKV*DH];
__device__ __align__(16) float g_v[(LL)Mtok*HKV*DH];
__device__ __align__(16) __half g_phiqh[(LL)Mtok*Hh*Ff];
__device__ __align__(16) __half g_phiql[(LL)Mtok*Hh*Ff];
__device__ __align__(16) float g_phik[(LL)Mtok*HKV*Ff];
__device__ __align__(16) float g_kvpart[(LL)32*32*Ff*DH];
__device__ __align__(16) float g_zpart[(LL)32*32*Ff];
__device__ __align__(16) __half g_kvTh[(LL)64*DH*Ff];
__device__ __align__(16) __half g_kvTl[(LL)64*DH*Ff];
__device__ __align__(16) float g_z[(LL)32*Ff];
__device__ __align__(16) float g_num[(LL)64*Ss*Ff];
__device__ __align__(16) __half g_attnh[(LL)Mtok*Dm];
__device__ __align__(16) float g_t1[(LL)Mtok*Dm];
__device__ __align__(16) float g_h[(LL)Mtok*Dm];
__device__ __align__(16) __half g_hh[(LL)Mtok*Dm];
__device__ __align__(16) __half g_acth[(LL)Mtok*DFF];
__device__ __align__(16) __half g_w1h[(LL)Rr*Dm];
__device__ __align__(16) __half g_w1l[(LL)Rr*Dm];
__device__ __align__(16) __half g_w2h[(LL)Rr*Dm];
__device__ __align__(16) __half g_w2l[(LL)Rr*Dm];
__device__ __align__(16) __half g_w3h[(LL)Dm*Rr];
__device__ __align__(16) __half g_w3l[(LL)Dm*Rr];
__device__ __align__(16) __half g_w4h[(LL)HKV*DH*Rr];
__device__ __align__(16) __half g_w4l[(LL)HKV*DH*Rr];
__device__ __align__(16) __half g_w5h[(LL)HKV*DH*Rr];
__device__ __align__(16) __half g_w5l[(LL)HKV*DH*Rr];
__device__ __align__(16) __half g_w6h[(LL)Dm*Dm];
__device__ __align__(16) __half g_w6l[(LL)Dm*Dm];
__device__ __align__(16) __half g_w7h[(LL)DFF*Dm];
__device__ __align__(16) __half g_w7l[(LL)DFF*Dm];
__device__ __align__(16) __half g_w8h[(LL)DFF*Dm];
__device__ __align__(16) __half g_w8l[(LL)DFF*Dm];
__device__ __align__(16) __half g_w9h[(LL)Dm*DFF];
__device__ __align__(16) __half g_w9l[(LL)Dm*DFF];

__device__ __forceinline__ void split2(float v, __half* ph, __half* pl){
    __half h=__float2half_rn(v); *ph=h; *pl=__float2half_rn(v-__half2float(h));}

__global__ __launch_bounds__(256) void convT(const float* __restrict__ W, __half* __restrict__ Wh, __half* __restrict__ Wl, int K, int N){
    __shared__ float t[32][33];
    int tx=threadIdx.x, ty=threadIdx.y, k0=blockIdx.y*32, n0=blockIdx.x*32;
    #pragma unroll
    for(int i=0;i<4;i++){int r=ty+i*8; t[r][tx]=W[(LL)(k0+r)*N+n0+tx];}
    __syncthreads();
    #pragma unroll
    for(int i=0;i<4;i++){int r=ty+i*8; LL o=(LL)(n0+r)*K+k0+tx; split2(t[tx][r],&Wh[o],&Wl[o]);}
}
__global__ __launch_bounds__(256) void convE(const float* __restrict__ X, __half* __restrict__ Xh, __half* __restrict__ Xl, LL n){
    LL i=((LL)blockIdx.x*256+threadIdx.x)*4; if(i>=n) return;
    float4 v=*(const float4*)&X[i];
    split2(v.x,&Xh[i],&Xl[i]); split2(v.y,&Xh[i+1],&Xl[i+1]); split2(v.z,&Xh[i+2],&Xl[i+2]); split2(v.w,&Xh[i+3],&Xl[i+3]);
}

// C[M,N]=A[M,K]@B[N,K]^T. PH3: AhBh+AhBl+AlBh; PH2: AhBh+AhBl. ST = pipeline stages (2 or 3).
template<int BN,int PH,int EPI,int OUTM,int ST>
__global__ __launch_bounds__(256) void tgemm(
    const __half* __restrict__ Ah, const __half* __restrict__ Al,
    const __half* __restrict__ Bh, const __half* __restrict__ Bl,
    const float* __restrict__ D, float* __restrict__ C,
    __half* __restrict__ Chi, __half* __restrict__ Clo,
    int K, int ldc, LL sA, LL sB, LL sC)
{
    extern __shared__ char smem[];
    const uint32_t sbase=smem_u32(smem);
    const int tid=threadIdx.x, wid=tid>>5, lane=tid&31;
    constexpr int ABYT=16384, BBYT=BN*128, NA=(PH==3)?2:1, BOFF=NA*ABYT, BUF=BOFF+2*BBYT;
    const int bm=blockIdx.y*128, bn=blockIdx.x*BN, bz=blockIdx.z;
    const __half* APh=Ah+(LL)bz*sA+(LL)bm*K;
    const __half* APl=(PH==3)?(Al+(LL)bz*sA+(LL)bm*K):nullptr;
    const __half* BPh=Bh+(LL)bz*sB+(LL)bn*K;
    const __half* BPl=Bl+(LL)bz*sB+(LL)bn*K;
    const int KT=K>>6;

    auto load=[&](int kt,int buf){
        uint32_t base=sbase+buf*BUF;
        const LL ko=(LL)kt*64;
        #pragma unroll
        for(int i=0;i<4;i++){
            int c=tid+i*256, r=c>>3, ch=c&7; uint32_t sw=SW128(r*128+ch*16);
            CPA16(base+sw, APh+(LL)r*K+ko+ch*8);
            if(PH==3) CPA16(base+ABYT+sw, APl+(LL)r*K+ko+ch*8);
        }
        #pragma unroll
        for(int i=0;i<BN/32;i++){
            int c=tid+i*256, r=c>>3, ch=c&7; uint32_t sw=SW128(r*128+ch*16);
            CPA16(base+BOFF+sw,      BPh+(LL)r*K+ko+ch*8);
            CPA16(base+BOFF+BBYT+sw, BPl+(LL)r*K+ko+ch*8);
        }
    };

    constexpr int WN=BN/4, NF=WN/8;
    const int g=lane>>2, tg=lane&3, wm=wid&1, wn=wid>>1;
    float acc[4][NF][4];
    #pragma unroll
    for(int i=0;i<4;i++)
        #pragma unroll
        for(int j=0;j<NF;j++){acc[i][j][0]=0.f;acc[i][j][1]=0.f;acc[i][j][2]=0.f;acc[i][j][3]=0.f;}

    const int aquad=lane>>3, alr=lane&7;
    const int arow = wm*64 + ((aquad&1)<<3) + alr;
    const int acol = (aquad>>1)<<4;
    const int brow2 = wn*WN + ((lane>>4)&1)*8 + (lane&7);
    const int bcol  = ((lane>>3)&1)<<4;

    load(0,0); CPCOMMIT();
    if(ST==3 && KT>1){ load(1,1); CPCOMMIT(); }
    for(int kt=0;kt<KT;kt++){
        if(ST==2){
            if(kt+1<KT){ load(kt+1,(kt+1)&1); CPCOMMIT(); CPWAIT(1); }
            else CPWAIT(0);
        } else {
            if(kt+2<KT){ load(kt+2,(kt+2)%3); CPCOMMIT(); CPWAIT(2); }
            else if(kt+1<KT) CPWAIT(1);
            else CPWAIT(0);
        }
        __syncthreads();
        const uint32_t cbase=sbase+(kt%ST)*BUF;
        #pragma unroll
        for(int ks=0;ks<4;ks++){
            uint32_t ahf[4][4], alf[4][4], bhf[NF][2], blf[NF][2];
            #pragma unroll
            for(int mf=0;mf<4;mf++){
                uint32_t ad=cbase+SW128((arow+mf*16)*128 + ks*32+acol);
                ldsm4(ahf[mf], ad);
                if(PH==3) ldsm4(alf[mf], ad+ABYT);
            }
            #pragma unroll
            for(int np=0;np<NF/2;np++){
                uint32_t bd=cbase+BOFF+SW128((brow2+np*16)*128 + ks*32+bcol);
                uint32_t t4[4];
                ldsm4(t4,bd);
                bhf[2*np][0]=t4[0];bhf[2*np][1]=t4[1];bhf[2*np+1][0]=t4[2];bhf[2*np+1][1]=t4[3];
                ldsm4(t4,bd+BBYT);
                blf[2*np][0]=t4[0];blf[2*np][1]=t4[1];blf[2*np+1][0]=t4[2];blf[2*np+1][1]=t4[3];
            }
            #pragma unroll
            for(int mf=0;mf<4;mf++)
                #pragma unroll
                for(int nf=0;nf<NF;nf++){
                    MMA(acc[mf][nf], ahf[mf], bhf[nf]);
                    MMA(acc[mf][nf], ahf[mf], blf[nf]);
                    if(PH==3) MMA(acc[mf][nf], alf[mf], bhf[nf]);
                }
        }
        __syncthreads();
    }

    #pragma unroll
    for(int mf=0;mf<4;mf++)
        #pragma unroll
        for(int nf=0;nf<NF;nf++)
            #pragma unroll
            for(int hr=0;hr<2;hr++){
                int r=bm+wm*64+mf*16+g+hr*8;
                int c=bn+wn*WN+nf*8+tg*2;
                LL idx=(LL)bz*sC+(LL)r*ldc+c;
                float v0=acc[mf][nf][hr*2], v1=acc[mf][nf][hr*2+1];
                if(EPI==1){float2 d2=*(const float2*)&D[idx]; v0+=d2.x; v1+=d2.y;}
                if(OUTM&1){float2 o2; o2.x=v0; o2.y=v1; *(float2*)&C[idx]=o2;}
                if(OUTM&2){
                    __half h0=__float2half_rn(v0), h1=__float2half_rn(v1);
                    *(__half2*)&Chi[idx]=__halves2half2(h0,h1);
                    *(__half2*)&Clo[idx]=__halves2half2(
                        __float2half_rn(v0-__half2float(h0)), __float2half_rn(v1-__half2float(h1)));
                }
                if(OUTM&4){
                    *(__half2*)&Chi[idx]=__halves2half2(__float2half_rn(v0),__float2half_rn(v1));
                }
            }
}

// Fused gate+up: act = (A@Wg^T) * silu(A@Wu^T). BM=256, BN=64, PH2, 3-stage, swizzled 1D grid.
__global__ __launch_bounds__(256) void tgemm2(
    const __half* __restrict__ Ah,
    const __half* __restrict__ Bgh, const __half* __restrict__ Bgl,
    const __half* __restrict__ Buh, const __half* __restrict__ Bul,
    __half* __restrict__ Co)
{
    extern __shared__ char smem[];
    const uint32_t sbase=smem_u32(smem);
    const int tid=threadIdx.x, wid=tid>>5, lane=tid&31;
    constexpr int ABYT=32768, BBYT=8192, BUF=ABYT+4*BBYT;  // 65536 per stage
    // swizzle: groups of 8 bm tiles sweep all 128 bn tiles (L2-resident working set)
    const int idx0=blockIdx.x;
    const int grp=idx0>>10, rem=idx0&1023;
    const int bm=(grp*8+(rem&7))*256, bn=(rem>>3)*64;
    const __half* AP=Ah+(LL)bm*Dm;
    const __half* Bg[2]={Bgh+(LL)bn*Dm, Bgl+(LL)bn*Dm};
    const __half* Bu[2]={Buh+(LL)bn*Dm, Bul+(LL)bn*Dm};
    const int KT=Dm>>6;

    auto load=[&](int kt,int buf){
        uint32_t base=sbase+buf*BUF;
        const LL ko=(LL)kt*64;
        #pragma unroll
        for(int i=0;i<8;i++){
            int c=tid+i*256, r=c>>3, ch=c&7; uint32_t sw=SW128(r*128+ch*16);
            CPA16(base+sw, AP+(LL)r*Dm+ko+ch*8);
        }
        #pragma unroll
        for(int i=0;i<2;i++){
            int c=tid+i*256, r=c>>3, ch=c&7; uint32_t sw=SW128(r*128+ch*16);
            CPA16(base+ABYT+sw,        Bg[0]+(LL)r*Dm+ko+ch*8);
            CPA16(base+ABYT+BBYT+sw,   Bg[1]+(LL)r*Dm+ko+ch*8);
            CPA16(base+ABYT+2*BBYT+sw, Bu[0]+(LL)r*Dm+ko+ch*8);
            CPA16(base+ABYT+3*BBYT+sw, Bu[1]+(LL)r*Dm+ko+ch*8);
        }
    };

    const int g=lane>>2, tg=lane&3, wm=wid&3, wn=wid>>2;
    float accg[4][4][4], accu[4][4][4];
    #pragma unroll
    for(int i=0;i<4;i++)
        #pragma unroll
        for(int j=0;j<4;j++)
            #pragma unroll
            for(int e=0;e<4;e++){accg[i][j][e]=0.f;accu[i][j][e]=0.f;}

    const int aquad=lane>>3, alr=lane&7;
    const int arow = wm*64 + ((aquad&1)<<3) + alr;
    const int acol = (aquad>>1)<<4;
    const int brow2 = wn*32 + ((lane>>4)&1)*8 + (lane&7);
    const int bcol  = ((lane>>3)&1)<<4;

    load(0,0); CPCOMMIT();
    load(1,1); CPCOMMIT();
    for(int kt=0;kt<KT;kt++){
        if(kt+2<KT){ load(kt+2,(kt+2)%3); CPCOMMIT(); CPWAIT(2); }
        else if(kt+1<KT) CPWAIT(1);
        else CPWAIT(0);
        __syncthreads();
        const uint32_t cbase=sbase+(kt%3)*BUF;
        #pragma unroll
        for(int ks=0;ks<4;ks++){
            uint32_t ahf[4][4], bgh[4][2], bgl[4][2], buh[4][2], bul[4][2];
            #pragma unroll
            for(int mf=0;mf<4;mf++)
                ldsm4(ahf[mf], cbase+SW128((arow+mf*16)*128 + ks*32+acol));
            #pragma unroll
            for(int np=0;np<2;np++){
                uint32_t bd=cbase+ABYT+SW128((brow2+np*16)*128 + ks*32+bcol);
                uint32_t t4[4];
                ldsm4(t4,bd);        bgh[2*np][0]=t4[0];bgh[2*np][1]=t4[1];bgh[2*np+1][0]=t4[2];bgh[2*np+1][1]=t4[3];
                ldsm4(t4,bd+BBYT);   bgl[2*np][0]=t4[0];bgl[2*np][1]=t4[1];bgl[2*np+1][0]=t4[2];bgl[2*np+1][1]=t4[3];
                ldsm4(t4,bd+2*BBYT); buh[2*np][0]=t4[0];buh[2*np][1]=t4[1];buh[2*np+1][0]=t4[2];buh[2*np+1][1]=t4[3];
                ldsm4(t4,bd+3*BBYT); bul[2*np][0]=t4[0];bul[2*np][1]=t4[1];bul[2*np+1][0]=t4[2];bul[2*np+1][1]=t4[3];
            }
            #pragma unroll
            for(int mf=0;mf<4;mf++)
                #pragma unroll
                for(int nf=0;nf<4;nf++){
                    MMA(accg[mf][nf], ahf[mf], bgh[nf]);
                    MMA(accg[mf][nf], ahf[mf], bgl[nf]);
                    MMA(accu[mf][nf], ahf[mf], buh[nf]);
                    MMA(accu[mf][nf], ahf[mf], bul[nf]);
                }
        }
        __syncthreads();
    }

    #pragma unroll
    for(int mf=0;mf<4;mf++)
        #pragma unroll
        for(int nf=0;nf<4;nf++)
            #pragma unroll
            for(int hr=0;hr<2;hr++){
                int r=bm+wm*64+mf*16+g+hr*8;
                int c=bn+wn*32+nf*8+tg*2;
                LL idx=(LL)r*DFF+c;
                float g0=accg[mf][nf][hr*2], g1=accg[mf][nf][hr*2+1];
                float u0=accu[mf][nf][hr*2], u1=accu[mf][nf][hr*2+1];
                float a0=g0*(u0/(1.f+expf(-u0))), a1=g1*(u1/(1.f+expf(-u1)));
                *(__half2*)&Co[idx]=__halves2half2(__float2half_rn(a0),__float2half_rn(a1));
            }
}

template<bool HILO>
__global__ __launch_bounds__(256) void phi_kernel(const float* __restrict__ qk, const float* __restrict__ omega,
    float* __restrict__ phi, __half* __restrict__ ph, __half* __restrict__ pl, int nheads, int estride)
{
    __shared__ float om[DH][KD]; __shared__ float qs[16][DH];
    const int h=blockIdx.y, t0=blockIdx.x*16, tid=threadIdx.x;
    #pragma unroll
    for(int i=0;i<8;i++){int fi=tid+i*256,d=fi>>4,c4=(fi&15)*4;*(float4*)&om[d][c4]=*(const float4*)&omega[d*KD+c4];}
    #pragma unroll
    for(int i=0;i<2;i++){int fi=tid+i*256,r=fi>>5,c4=(fi&31)*4;*(float4*)&qs[r][c4]=*(const float4*)&qk[(LL)(t0+r)*estride+h*DH+c4];}
    __syncthreads();
    const int tl=tid>>4, kg=(tid&15)*4, t=t0+tl, b=t/Ss, sr=t-b*Ss;
    const LL base=((LL)(b*nheads+h)*Ss+sr)*Ff;
    #pragma unroll
    for(int kk=0;kk<4;kk++){
        int kc=kg+kk; float pr=0.f;
        #pragma unroll
        for(int d=0;d<DH;d++) pr+=qs[tl][d]*om[d][kc];
        float sv,cv; __sincosf(pr,&sv,&cv);
        float vc=cv*0.125f, vs=sv*0.125f;
        if(HILO){split2(vc,&ph[base+kc],&pl[base+kc]); split2(vs,&ph[base+KD+kc],&pl[base+KD+kc]);}
        else{phi[base+kc]=vc; phi[base+KD+kc]=vs;}
    }
}

__global__ __launch_bounds__(256) void kv_split(const float* __restrict__ phik, const float* __restrict__ v, float* __restrict__ kvpart){
    const int split=blockIdx.x, bh2=blockIdx.z, b=bh2>>3, hk=bh2&7;
    const float* Pk=phik+(LL)bh2*Ss*Ff;
    const float* V=v+(LL)b*Ss*(HKV*DH)+hk*DH;
    __shared__ float As[16][128]; __shared__ float Bs[16][128];
    const int tid=threadIdx.x, tc=tid&15, tr=tid>>4, lr=tid>>5, lc=(tid&31)<<2;
    float acc[8][8];
    #pragma unroll
    for(int i=0;i<8;i++)
        #pragma unroll
        for(int j=0;j<8;j++) acc[i][j]=0.f;
    for(int ks=0;ks<8;ks++){
        int s0=split*128+ks*16;
        #pragma unroll
        for(int pp=0;pp<2;pp++){int r=lr+pp*8;
            *(float4*)&As[r][lc]=*(const float4*)&Pk[(LL)(s0+r)*Ff+lc];
            *(float4*)&Bs[r][lc]=*(const float4*)&V[(LL)(s0+r)*(HKV*DH)+lc];}
        __syncthreads();
        #pragma unroll
        for(int kk=0;kk<16;kk++){
            float ar[8],br[8];
            *(float4*)&ar[0]=*(const float4*)&As[kk][tr*8]; *(float4*)&ar[4]=*(const float4*)&As[kk][tr*8+4];
            *(float4*)&br[0]=*(const float4*)&Bs[kk][tc*8]; *(float4*)&br[4]=*(const float4*)&Bs[kk][tc*8+4];
            #pragma unroll
            for(int i=0;i<8;i++)
                #pragma unroll
                for(int j=0;j<8;j++) acc[i][j]+=ar[i]*br[j];
        }
        __syncthreads();
    }
    float* o=kvpart+((LL)bh2*32+split)*(Ff*DH);
    #pragma unroll
    for(int i=0;i<8;i++)
        #pragma unroll
        for(int j=0;j<8;j++) o[(tr*8+i)*DH+tc*8+j]=acc[i][j];
}
__global__ void z_split(const float* __restrict__ phik, float* __restrict__ zp){
    const int split=blockIdx.x, bh2=blockIdx.y, f=threadIdx.x;
    const float* P=phik+(LL)bh2*Ss*Ff; float s=0.f;
    for(int i=0;i<128;i++) s+=P[(LL)(split*128+i)*Ff+f];
    zp[((LL)bh2*32+split)*Ff+f]=s;
}
__global__ void kv_reduce(const float* __restrict__ kvp, __half* __restrict__ kvh, __half* __restrict__ kvl){
    const int bh=blockIdx.y, bh2=(bh>>4)*8+((bh&15)>>1);
    const int idx=blockIdx.x*128+threadIdx.x;
    const float* p=kvp+(LL)bh2*32*(Ff*DH)+idx;
    float s=0.f;
    #pragma unroll
    for(int sp=0;sp<32;sp++) s+=p[(LL)sp*(Ff*DH)];
    int f=idx>>7, d=idx&127;
    LL o=(LL)bh*(DH*Ff)+(LL)d*Ff+f;
    split2(s,&kvh[o],&kvl[o]);
}
__global__ void z_reduce(const float* __restrict__ zp, float* __restrict__ z){
    const int bh2=blockIdx.x, f=threadIdx.x; float s=0.f;
    #pragma unroll
    for(int sp=0;sp<32;sp++) s+=zp[((LL)bh2*32+sp)*Ff+f];
    z[bh2*Ff+f]=s;
}
__global__ __launch_bounds__(128) void divide_k(const __half* __restrict__ pqh, const __half* __restrict__ pql,
    const float* __restrict__ z, const float* __restrict__ num, __half* __restrict__ ah){
    const int chunk=blockIdx.x, bh=blockIdx.y, tid=threadIdx.x;
    const int b=bh>>4, h=bh&15, bh2=b*8+(h>>1);
    __shared__ float zs[128]; __shared__ float red[4];
    zs[tid]=z[bh2*Ff+tid]; __syncthreads();
    for(int i=0;i<32;i++){
        int s=chunk*32+i;
        LL off=((LL)bh*Ss+s)*Ff+tid;
        float pq=__half2float(pqh[off])+__half2float(pql[off]);
        float pv=pq*zs[tid];
        #pragma unroll
        for(int o=16;o>0;o>>=1) pv+=__shfl_down_sync(0xffffffffu,pv,o);
        if((tid&31)==0) red[tid>>5]=pv;
        __syncthreads();
        float den=red[0]+red[1]+red[2]+red[3];
        float a=num[off]/(den+1e-6f);
        ah[((LL)(b*Ss+s))*Dm+h*DH+tid]=__float2half_rn(a);
        __syncthreads();
    }
}
template<bool HILO>
__global__ __launch_bounds__(256) void ln_k(const float* __restrict__ in, const float* __restrict__ g, const float* __restrict__ be,
    float* __restrict__ out, __half* __restrict__ oh){
    const int row=blockIdx.x, tid=threadIdx.x;
    const float* p=in+(LL)row*Dm;
    float4 a=*(const float4*)&p[tid*4], b4=*(const float4*)&p[1024+tid*4];
    float s=a.x+a.y+a.z+a.w+b4.x+b4.y+b4.z+b4.w;
    float q=a.x*a.x+a.y*a.y+a.z*a.z+a.w*a.w+b4.x*b4.x+b4.y*b4.y+b4.z*b4.z+b4.w*b4.w;
    __shared__ float rs[8], rq[8];
    #pragma unroll
    for(int o=16;o>0;o>>=1){s+=__shfl_down_sync(0xffffffffu,s,o);q+=__shfl_down_sync(0xffffffffu,q,o);}
    if((tid&31)==0){rs[tid>>5]=s;rq[tid>>5]=q;}
    __syncthreads();
    float S=0.f,Q=0.f;
    #pragma unroll
    for(int w=0;w<8;w++){S+=rs[w];Q+=rq[w];}
    float mu=S/(float)Dm, var=Q/(float)Dm-mu*mu, rstd=rsqrtf(var+1e-5f);
    float* po=out+(LL)row*Dm;
    #pragma unroll
    for(int hf=0;hf<2;hf++){
        int c0=hf*1024+tid*4;
        float4 vv=hf?b4:a;
        float4 g4=*(const float4*)&g[c0], bt=*(const float4*)&be[c0];
        float4 o4;
        o4.x=(vv.x-mu)*rstd*g4.x+bt.x; o4.y=(vv.y-mu)*rstd*g4.y+bt.y;
        o4.z=(vv.z-mu)*rstd*g4.z+bt.z; o4.w=(vv.w-mu)*rstd*g4.w+bt.w;
        *(float4*)&po[c0]=o4;
        if(HILO){LL ix=(LL)row*Dm+c0;
            *(__half2*)&oh[ix]  =__halves2half2(__float2half_rn(o4.x),__float2half_rn(o4.y));
            *(__half2*)&oh[ix+2]=__halves2half2(__float2half_rn(o4.z),__float2half_rn(o4.w));}
    }
}

static inline int ssz(int BN,int PH,int ST){ return ST*(((PH==3)?2:1)*16384 + 2*BN*128); }

extern "C" void kernel_launch(void* const* d_in, const int* in_sizes, int n_in, void* d_out, int out_size)
{
    const float* x=(const float*)d_in[0];
    const float* W_dq=(const float*)d_in[1];
    const float* W_uq=(const float*)d_in[2];
    const float* W_dkv=(const float*)d_in[3];
    const float* W_uk=(const float*)d_in[4];
    const float* W_uv=(const float*)d_in[5];
    const float* omega=(const float*)d_in[6];
    const float* W_o=(const float*)d_in[7];
    const float* ln1g=(const float*)d_in[8];
    const float* ln1b=(const float*)d_in[9];
    const float* gW=(const float*)d_in[10];
    const float* uW=(const float*)d_in[11];
    const float* dW=(const float*)d_in[12];
    const float* ln2g=(const float*)d_in[13];
    const float* ln2b=(const float*)d_in[14];
    float* out=(float*)d_out;

    #define GA(T,p,s) T* p; cudaGetSymbolAddress((void**)&p, s)
    GA(__half,xh,g_xh); GA(__half,xl,g_xl);
    GA(__half,cqh,g_cqh); GA(__half,cql,g_cql); GA(__half,ckvh,g_ckvh); GA(__half,ckvl,g_ckvl);
    GA(float,q,g_q); GA(float,kk,g_k); GA(float,vv,g_v);
    GA(__half,pqh,g_phiqh); GA(__half,pql,g_phiql); GA(float,pk,g_phik);
    GA(float,kvp,g_kvpart); GA(float,zp,g_zpart);
    GA(__half,kvh,g_kvTh); GA(__half,kvl,g_kvTl);
    GA(float,z,g_z); GA(float,num,g_num);
    GA(__half,ath,g_attnh);
    GA(float,t1,g_t1); GA(float,hb,g_h);
    GA(__half,hh,g_hh);
    GA(__half,acth,g_acth);
    GA(__half,w1h,g_w1h); GA(__half,w1l,g_w1l); GA(__half,w2h,g_w2h); GA(__half,w2l,g_w2l);
    GA(__half,w3h,g_w3h); GA(__half,w3l,g_w3l); GA(__half,w4h,g_w4h); GA(__half,w4l,g_w4l);
    GA(__half,w5h,g_w5h); GA(__half,w5l,g_w5l); GA(__half,w6h,g_w6h); GA(__half,w6l,g_w6l);
    GA(__half,w7h,g_w7h); GA(__half,w7l,g_w7l); GA(__half,w8h,g_w8h); GA(__half,w8l,g_w8l);
    GA(__half,w9h,g_w9h); GA(__half,w9l,g_w9l);
    #undef GA

    cudaFuncSetAttribute(tgemm<64,3,0,2,3>,  cudaFuncAttributeMaxDynamicSharedMemorySize, ssz(64,3,3));
    cudaFuncSetAttribute(tgemm<128,3,0,1,2>, cudaFuncAttributeMaxDynamicSharedMemorySize, ssz(128,3,2));
    cudaFuncSetAttribute(tgemm<256,2,1,1,2>, cudaFuncAttributeMaxDynamicSharedMemorySize, ssz(256,2,2));
    cudaFuncSetAttribute(tgemm2, cudaFuncAttributeMaxDynamicSharedMemorySize, 196608);

    dim3 cb(32,8);
    convT<<<dim3(Rr/32,Dm/32),cb>>>(W_dq,w1h,w1l,Dm,Rr);                    // 0
    convT<<<dim3(Rr/32,Dm/32),cb>>>(W_dkv,w2h,w2l,Dm,Rr);                   // 1
    convE<<<(int)(((LL)Mtok*Dm/4+255)/256),256>>>(x,xh,xl,(LL)Mtok*Dm);     // 2
    tgemm<64,3,0,2,3><<<dim3(1,Mtok/128),256,ssz(64,3,3)>>>(xh,xl,w1h,w1l,nullptr,nullptr,cqh,cql,Dm,Rr,0,0,0); // 3
    convT<<<dim3(Dm/32,Rr/32),cb>>>(W_uq,w3h,w3l,Rr,Dm);                    // 4
    tgemm<64,3,0,2,3><<<dim3(1,Mtok/128),256,ssz(64,3,3)>>>(xh,xl,w2h,w2l,nullptr,nullptr,ckvh,ckvl,Dm,Rr,0,0,0); // 5 <- ncu
    convT<<<dim3(HKV*DH/32,Rr/32),cb>>>(W_uk,w4h,w4l,Rr,HKV*DH);
    convT<<<dim3(HKV*DH/32,Rr/32),cb>>>(W_uv,w5h,w5l,Rr,HKV*DH);
    convT<<<dim3(Dm/32,Dm/32),cb>>>(W_o,w6h,w6l,Dm,Dm);
    convT<<<dim3(DFF/32,Dm/32),cb>>>(gW,w7h,w7l,Dm,DFF);
    convT<<<dim3(DFF/32,Dm/32),cb>>>(uW,w8h,w8l,Dm,DFF);
    convT<<<dim3(Dm/32,DFF/32),cb>>>(dW,w9h,w9l,DFF,Dm);

    tgemm<128,3,0,1,2><<<dim3(Dm/128,Mtok/128),256,ssz(128,3,2)>>>(cqh,cql,w3h,w3l,nullptr,q,nullptr,nullptr,Rr,Dm,0,0,0);
    tgemm<128,3,0,1,2><<<dim3(HKV*DH/128,Mtok/128),256,ssz(128,3,2)>>>(ckvh,ckvl,w4h,w4l,nullptr,kk,nullptr,nullptr,Rr,HKV*DH,0,0,0);
    tgemm<128,3,0,1,2><<<dim3(HKV*DH/128,Mtok/128),256,ssz(128,3,2)>>>(ckvh,ckvl,w5h,w5l,nullptr,vv,nullptr,nullptr,Rr,HKV*DH,0,0,0);

    phi_kernel<true><<<dim3(Mtok/16,Hh),256>>>(q,omega,nullptr,pqh,pql,Hh,Dm);
    phi_kernel<false><<<dim3(Mtok/16,HKV),256>>>(kk,omega,pk,nullptr,nullptr,HKV,HKV*DH);

    kv_split<<<dim3(32,1,32),256>>>(pk,vv,kvp);
    z_split<<<dim3(32,32),128>>>(pk,zp);
    kv_reduce<<<dim3(Ff*DH/128,64),128>>>(kvp,kvh,kvl);
    z_reduce<<<32,128>>>(zp,z);

    tgemm<128,3,0,1,2><<<dim3(1,Ss/128,64),256,ssz(128,3,2)>>>(pqh,pql,kvh,kvl,nullptr,num,nullptr,nullptr,Ff,DH,(LL)Ss*Ff,(LL)DH*Ff,(LL)Ss*DH);
    divide_k<<<dim3(Ss/32,64),128>>>(pqh,pql,z,num,ath);

    tgemm<256,2,1,1,2><<<dim3(Dm/256,Mtok/128),256,ssz(256,2,2)>>>(ath,nullptr,w6h,w6l,x,t1,nullptr,nullptr,Dm,Dm,0,0,0);
    ln_k<true><<<Mtok,256>>>(t1,ln1g,ln1b,hb,hh);

    tgemm2<<<8192,256,196608>>>(hh,w7h,w7l,w8h,w8l,acth);
    tgemm<256,2,1,1,2><<<dim3(Dm/256,Mtok/128),256,ssz(256,2,2)>>>(acth,nullptr,w9h,w9l,hb,t1,nullptr,nullptr,DFF,Dm,0,0,0);
    ln_k<false><<<Mtok,256>>>(t1,ln2g,ln2b,out,nullptr);
}

// round 12
// speedup vs baseline: 1.5192x; 1.5192x over previous
#include <cuda_runtime.h>
#include <cuda_fp16.h>
#include <cstdint>
#include <math.h>
typedef long long LL;

constexpr int Bb=4, Ss=4096, Dm=2048, DFF=8192, Hh=16, HKV=8, DH=128, Rr=64, KD=64, Ff=128;
constexpr int Mtok=Bb*Ss;

__device__ __forceinline__ uint32_t smem_u32(const void* p){uint32_t a;asm("{ .reg .u64 t; cvta.to.shared.u64 t, %1; cvt.u32.u64 %0, t; }":"=r"(a):"l"(p));return a;}
#define SW128(o) ((o) ^ (((o) >> 3) & 0x70))
#define CPA16(dst,src) asm volatile("cp.async.cg.shared.global [%0], [%1], 16;"::"r"(dst),"l"(src):"memory")
#define CPCOMMIT() asm volatile("cp.async.commit_group;":::"memory")
#define CPWAIT(n) asm volatile("cp.async.wait_group %0;"::"n"(n):"memory")
__device__ __forceinline__ void ldsm4(uint32_t* r, uint32_t a){
    asm volatile("ldmatrix.sync.aligned.m8n8.x4.shared.b16 {%0,%1,%2,%3}, [%4];"
        :"=r"(r[0]),"=r"(r[1]),"=r"(r[2]),"=r"(r[3]):"r"(a));}
#define MMA(d,a,b) asm volatile("mma.sync.aligned.m16n8k16.row.col.f32.f16.f16.f32 {%0,%1,%2,%3},{%4,%5,%6,%7},{%8,%9},{%0,%1,%2,%3};" \
  :"+f"((d)[0]),"+f"((d)[1]),"+f"((d)[2]),"+f"((d)[3]) \
  :"r"((a)[0]),"r"((a)[1]),"r"((a)[2]),"r"((a)[3]),"r"((b)[0]),"r"((b)[1]))

__device__ __align__(16) __half g_xh[(LL)Mtok*Dm];
__device__ __align__(16) __half g_xl[(LL)Mtok*Dm];
__device__ __align__(16) __half g_cqh[(LL)Mtok*Rr];
__device__ __align__(16) __half g_cql[(LL)Mtok*Rr];
__device__ __align__(16) __half g_ckvh[(LL)Mtok*Rr];
__device__ __align__(16) __half g_ckvl[(LL)Mtok*Rr];
__device__ __align__(16) float g_q[(LL)Mtok*Dm];
__device__ __align__(16) float g_k[(LL)Mtok*HKV*DH];
__device__ __align__(16) float g_v[(LL)Mtok*HKV*DH];
__device__ __align__(16) __half g_phiqh[(LL)Mtok*Hh*Ff];
__device__ __align__(16) __half g_phiql[(LL)Mtok*Hh*Ff];
__device__ __align__(16) float g_phik[(LL)Mtok*HKV*Ff];
__device__ __align__(16) float g_kvpart[(LL)32*32*Ff*DH];
__device__ __align__(16) float g_zpart[(LL)32*32*Ff];
__device__ __align__(16) __half g_kvTh[(LL)64*DH*Ff];
__device__ __align__(16) __half g_kvTl[(LL)64*DH*Ff];
__device__ __align__(16) float g_z[(LL)32*Ff];
__device__ __align__(16) float g_num[(LL)64*Ss*Ff];
__device__ __align__(16) __half g_attnh[(LL)Mtok*Dm];
__device__ __align__(16) float g_t1[(LL)Mtok*Dm];
__device__ __align__(16) float g_h[(LL)Mtok*Dm];
__device__ __align__(16) __half g_hh[(LL)Mtok*Dm];
__device__ __align__(16) __half g_acth[(LL)Mtok*DFF];
__device__ __align__(16) __half g_w1h[(LL)Rr*Dm];
__device__ __align__(16) __half g_w1l[(LL)Rr*Dm];
__device__ __align__(16) __half g_w2h[(LL)Rr*Dm];
__device__ __align__(16) __half g_w2l[(LL)Rr*Dm];
__device__ __align__(16) __half g_w3h[(LL)Dm*Rr];
__device__ __align__(16) __half g_w3l[(LL)Dm*Rr];
__device__ __align__(16) __half g_w4h[(LL)HKV*DH*Rr];
__device__ __align__(16) __half g_w4l[(LL)HKV*DH*Rr];
__device__ __align__(16) __half g_w5h[(LL)HKV*DH*Rr];
__device__ __align__(16) __half g_w5l[(LL)HKV*DH*Rr];
__device__ __align__(16) __half g_w6h[(LL)Dm*Dm];
__device__ __align__(16) __half g_w7h[(LL)DFF*Dm];
__device__ __align__(16) __half g_w8h[(LL)DFF*Dm];
__device__ __align__(16) __half g_w9h[(LL)Dm*DFF];

__device__ __forceinline__ void split2(float v, __half* ph, __half* pl){
    __half h=__float2half_rn(v); *ph=h; *pl=__float2half_rn(v-__half2float(h));}

template<bool WRL>
__global__ __launch_bounds__(256) void convT(const float* __restrict__ W, __half* __restrict__ Wh, __half* __restrict__ Wl, int K, int N){
    __shared__ float t[32][33];
    int tx=threadIdx.x, ty=threadIdx.y, k0=blockIdx.y*32, n0=blockIdx.x*32;
    #pragma unroll
    for(int i=0;i<4;i++){int r=ty+i*8; t[r][tx]=W[(LL)(k0+r)*N+n0+tx];}
    __syncthreads();
    #pragma unroll
    for(int i=0;i<4;i++){
        int r=ty+i*8; LL o=(LL)(n0+r)*K+k0+tx; float v=t[tx][r];
        if(WRL) split2(v,&Wh[o],&Wl[o]);
        else Wh[o]=__float2half_rn(v);
    }
}
__global__ __launch_bounds__(256) void convE(const float* __restrict__ X, __half* __restrict__ Xh, __half* __restrict__ Xl, LL n){
    LL i=((LL)blockIdx.x*256+threadIdx.x)*4; if(i>=n) return;
    float4 v=*(const float4*)&X[i];
    split2(v.x,&Xh[i],&Xl[i]); split2(v.y,&Xh[i+1],&Xl[i+1]); split2(v.z,&Xh[i+2],&Xl[i+2]); split2(v.w,&Xh[i+3],&Xl[i+3]);
}

// C[M,N]=A[M,K]@B[N,K]^T. PH3: AhBh+AhBl+AlBh; PH2: AhBh+AhBl; PH1: AhBh only.
template<int BN,int PH,int EPI,int OUTM,int ST>
__global__ __launch_bounds__(256) void tgemm(
    const __half* __restrict__ Ah, const __half* __restrict__ Al,
    const __half* __restrict__ Bh, const __half* __restrict__ Bl,
    const float* __restrict__ D, float* __restrict__ C,
    __half* __restrict__ Chi, __half* __restrict__ Clo,
    int K, int ldc, LL sA, LL sB, LL sC)
{
    extern __shared__ char smem[];
    const uint32_t sbase=smem_u32(smem);
    const int tid=threadIdx.x, wid=tid>>5, lane=tid&31;
    constexpr int ABYT=16384, BBYT=BN*128, NA=(PH==3)?2:1, NB=(PH>=2)?2:1;
    constexpr int BOFF=NA*ABYT, BUF=BOFF+NB*BBYT;
    const int bm=blockIdx.y*128, bn=blockIdx.x*BN, bz=blockIdx.z;
    const __half* APh=Ah+(LL)bz*sA+(LL)bm*K;
    const __half* APl=(PH==3)?(Al+(LL)bz*sA+(LL)bm*K):nullptr;
    const __half* BPh=Bh+(LL)bz*sB+(LL)bn*K;
    const __half* BPl=(PH>=2)?(Bl+(LL)bz*sB+(LL)bn*K):nullptr;
    const int KT=K>>6;

    auto load=[&](int kt,int buf){
        uint32_t base=sbase+buf*BUF;
        const LL ko=(LL)kt*64;
        #pragma unroll
        for(int i=0;i<4;i++){
            int c=tid+i*256, r=c>>3, ch=c&7; uint32_t sw=SW128(r*128+ch*16);
            CPA16(base+sw, APh+(LL)r*K+ko+ch*8);
            if(PH==3) CPA16(base+ABYT+sw, APl+(LL)r*K+ko+ch*8);
        }
        #pragma unroll
        for(int i=0;i<BN/32;i++){
            int c=tid+i*256, r=c>>3, ch=c&7; uint32_t sw=SW128(r*128+ch*16);
            CPA16(base+BOFF+sw, BPh+(LL)r*K+ko+ch*8);
            if(PH>=2) CPA16(base+BOFF+BBYT+sw, BPl+(LL)r*K+ko+ch*8);
        }
    };

    constexpr int WN=BN/4, NF=WN/8;
    const int g=lane>>2, tg=lane&3, wm=wid&1, wn=wid>>1;
    float acc[4][NF][4];
    #pragma unroll
    for(int i=0;i<4;i++)
        #pragma unroll
        for(int j=0;j<NF;j++){acc[i][j][0]=0.f;acc[i][j][1]=0.f;acc[i][j][2]=0.f;acc[i][j][3]=0.f;}

    const int aquad=lane>>3, alr=lane&7;
    const int arow = wm*64 + ((aquad&1)<<3) + alr;
    const int acol = (aquad>>1)<<4;
    const int brow2 = wn*WN + ((lane>>4)&1)*8 + (lane&7);
    const int bcol  = ((lane>>3)&1)<<4;

    load(0,0); CPCOMMIT();
    if(ST==3 && KT>1){ load(1,1); CPCOMMIT(); }
    for(int kt=0;kt<KT;kt++){
        if(ST==2){
            if(kt+1<KT){ load(kt+1,(kt+1)&1); CPCOMMIT(); CPWAIT(1); }
            else CPWAIT(0);
        } else {
            if(kt+2<KT){ load(kt+2,(kt+2)%3); CPCOMMIT(); CPWAIT(2); }
            else if(kt+1<KT) CPWAIT(1);
            else CPWAIT(0);
        }
        __syncthreads();
        const uint32_t cbase=sbase+(kt%ST)*BUF;
        #pragma unroll
        for(int ks=0;ks<4;ks++){
            uint32_t ahf[4][4], alf[4][4], bhf[NF][2], blf[NF][2];
            #pragma unroll
            for(int mf=0;mf<4;mf++){
                uint32_t ad=cbase+SW128((arow+mf*16)*128 + ks*32+acol);
                ldsm4(ahf[mf], ad);
                if(PH==3) ldsm4(alf[mf], ad+ABYT);
            }
            #pragma unroll
            for(int np=0;np<NF/2;np++){
                uint32_t bd=cbase+BOFF+SW128((brow2+np*16)*128 + ks*32+bcol);
                uint32_t t4[4];
                ldsm4(t4,bd);
                bhf[2*np][0]=t4[0];bhf[2*np][1]=t4[1];bhf[2*np+1][0]=t4[2];bhf[2*np+1][1]=t4[3];
                if(PH>=2){
                    ldsm4(t4,bd+BBYT);
                    blf[2*np][0]=t4[0];blf[2*np][1]=t4[1];blf[2*np+1][0]=t4[2];blf[2*np+1][1]=t4[3];
                }
            }
            #pragma unroll
            for(int mf=0;mf<4;mf++)
                #pragma unroll
                for(int nf=0;nf<NF;nf++){
                    MMA(acc[mf][nf], ahf[mf], bhf[nf]);
                    if(PH>=2) MMA(acc[mf][nf], ahf[mf], blf[nf]);
                    if(PH==3) MMA(acc[mf][nf], alf[mf], bhf[nf]);
                }
        }
        __syncthreads();
    }

    #pragma unroll
    for(int mf=0;mf<4;mf++)
        #pragma unroll
        for(int nf=0;nf<NF;nf++)
            #pragma unroll
            for(int hr=0;hr<2;hr++){
                int r=bm+wm*64+mf*16+g+hr*8;
                int c=bn+wn*WN+nf*8+tg*2;
                LL idx=(LL)bz*sC+(LL)r*ldc+c;
                float v0=acc[mf][nf][hr*2], v1=acc[mf][nf][hr*2+1];
                if(EPI==1){float2 d2=*(const float2*)&D[idx]; v0+=d2.x; v1+=d2.y;}
                if(OUTM&1){float2 o2; o2.x=v0; o2.y=v1; *(float2*)&C[idx]=o2;}
                if(OUTM&2){
                    __half h0=__float2half_rn(v0), h1=__float2half_rn(v1);
                    *(__half2*)&Chi[idx]=__halves2half2(h0,h1);
                    *(__half2*)&Clo[idx]=__halves2half2(
                        __float2half_rn(v0-__half2float(h0)), __float2half_rn(v1-__half2float(h1)));
                }
                if(OUTM&4){
                    *(__half2*)&Chi[idx]=__halves2half2(__float2half_rn(v0),__float2half_rn(v1));
                }
            }
}

// Fused gate+up: act = (A@Wg^T) * silu(A@Wu^T). BM=256, BN=64, fp16 single-phase, 2-stage (96KB -> 2 CTA/SM).
__global__ __launch_bounds__(256) void tgemm2(
    const __half* __restrict__ Ah,
    const __half* __restrict__ Bgh, const __half* __restrict__ Buh,
    __half* __restrict__ Co)
{
    extern __shared__ char smem[];
    const uint32_t sbase=smem_u32(smem);
    const int tid=threadIdx.x, wid=tid>>5, lane=tid&31;
    constexpr int ABYT=32768, BBYT=8192, BUF=ABYT+2*BBYT;  // 49152/stage
    const int idx0=blockIdx.x;
    const int grp=idx0>>10, rem=idx0&1023;
    const int bm=(grp*8+(rem&7))*256, bn=(rem>>3)*64;
    const __half* AP=Ah+(LL)bm*Dm;
    const __half* Bg=Bgh+(LL)bn*Dm;
    const __half* Bu=Buh+(LL)bn*Dm;
    const int KT=Dm>>6;

    auto load=[&](int kt,int buf){
        uint32_t base=sbase+buf*BUF;
        const LL ko=(LL)kt*64;
        #pragma unroll
        for(int i=0;i<8;i++){
            int c=tid+i*256, r=c>>3, ch=c&7; uint32_t sw=SW128(r*128+ch*16);
            CPA16(base+sw, AP+(LL)r*Dm+ko+ch*8);
        }
        #pragma unroll
        for(int i=0;i<2;i++){
            int c=tid+i*256, r=c>>3, ch=c&7; uint32_t sw=SW128(r*128+ch*16);
            CPA16(base+ABYT+sw,      Bg+(LL)r*Dm+ko+ch*8);
            CPA16(base+ABYT+BBYT+sw, Bu+(LL)r*Dm+ko+ch*8);
        }
    };

    const int g=lane>>2, tg=lane&3, wm=wid&3, wn=wid>>2;
    float accg[4][4][4], accu[4][4][4];
    #pragma unroll
    for(int i=0;i<4;i++)
        #pragma unroll
        for(int j=0;j<4;j++)
            #pragma unroll
            for(int e=0;e<4;e++){accg[i][j][e]=0.f;accu[i][j][e]=0.f;}

    const int aquad=lane>>3, alr=lane&7;
    const int arow = wm*64 + ((aquad&1)<<3) + alr;
    const int acol = (aquad>>1)<<4;
    const int brow2 = wn*32 + ((lane>>4)&1)*8 + (lane&7);
    const int bcol  = ((lane>>3)&1)<<4;

    load(0,0); CPCOMMIT();
    for(int kt=0;kt<KT;kt++){
        if(kt+1<KT){ load(kt+1,(kt+1)&1); CPCOMMIT(); CPWAIT(1); }
        else CPWAIT(0);
        __syncthreads();
        const uint32_t cbase=sbase+(kt&1)*BUF;
        #pragma unroll
        for(int ks=0;ks<4;ks++){
            uint32_t ahf[4][4], bgf[4][2], buf_[4][2];
            #pragma unroll
            for(int mf=0;mf<4;mf++)
                ldsm4(ahf[mf], cbase+SW128((arow+mf*16)*128 + ks*32+acol));
            #pragma unroll
            for(int np=0;np<2;np++){
                uint32_t bd=cbase+ABYT+SW128((brow2+np*16)*128 + ks*32+bcol);
                uint32_t t4[4];
                ldsm4(t4,bd);      bgf[2*np][0]=t4[0];bgf[2*np][1]=t4[1];bgf[2*np+1][0]=t4[2];bgf[2*np+1][1]=t4[3];
                ldsm4(t4,bd+BBYT); buf_[2*np][0]=t4[0];buf_[2*np][1]=t4[1];buf_[2*np+1][0]=t4[2];buf_[2*np+1][1]=t4[3];
            }
            #pragma unroll
            for(int mf=0;mf<4;mf++)
                #pragma unroll
                for(int nf=0;nf<4;nf++){
                    MMA(accg[mf][nf], ahf[mf], bgf[nf]);
                    MMA(accu[mf][nf], ahf[mf], buf_[nf]);
                }
        }
        __syncthreads();
    }

    #pragma unroll
    for(int mf=0;mf<4;mf++)
        #pragma unroll
        for(int nf=0;nf<4;nf++)
            #pragma unroll
            for(int hr=0;hr<2;hr++){
                int r=bm+wm*64+mf*16+g+hr*8;
                int c=bn+wn*32+nf*8+tg*2;
                LL idx=(LL)r*DFF+c;
                float g0=accg[mf][nf][hr*2], g1=accg[mf][nf][hr*2+1];
                float u0=accu[mf][nf][hr*2], u1=accu[mf][nf][hr*2+1];
                float a0=g0*(u0/(1.f+expf(-u0))), a1=g1*(u1/(1.f+expf(-u1)));
                *(__half2*)&Co[idx]=__halves2half2(__float2half_rn(a0),__float2half_rn(a1));
            }
}

template<bool HILO>
__global__ __launch_bounds__(256) void phi_kernel(const float* __restrict__ qk, const float* __restrict__ omega,
    float* __restrict__ phi, __half* __restrict__ ph, __half* __restrict__ pl, int nheads, int estride)
{
    __shared__ float om[DH][KD]; __shared__ float qs[16][DH];
    const int h=blockIdx.y, t0=blockIdx.x*16, tid=threadIdx.x;
    #pragma unroll
    for(int i=0;i<8;i++){int fi=tid+i*256,d=fi>>4,c4=(fi&15)*4;*(float4*)&om[d][c4]=*(const float4*)&omega[d*KD+c4];}
    #pragma unroll
    for(int i=0;i<2;i++){int fi=tid+i*256,r=fi>>5,c4=(fi&31)*4;*(float4*)&qs[r][c4]=*(const float4*)&qk[(LL)(t0+r)*estride+h*DH+c4];}
    __syncthreads();
    const int tl=tid>>4, kg=(tid&15)*4, t=t0+tl, b=t/Ss, sr=t-b*Ss;
    const LL base=((LL)(b*nheads+h)*Ss+sr)*Ff;
    #pragma unroll
    for(int kk=0;kk<4;kk++){
        int kc=kg+kk; float pr=0.f;
        #pragma unroll
        for(int d=0;d<DH;d++) pr+=qs[tl][d]*om[d][kc];
        float sv,cv; __sincosf(pr,&sv,&cv);
        float vc=cv*0.125f, vs=sv*0.125f;
        if(HILO){split2(vc,&ph[base+kc],&pl[base+kc]); split2(vs,&ph[base+KD+kc],&pl[base+KD+kc]);}
        else{phi[base+kc]=vc; phi[base+KD+kc]=vs;}
    }
}

__global__ __launch_bounds__(256) void kv_split(const float* __restrict__ phik, const float* __restrict__ v, float* __restrict__ kvpart){
    const int split=blockIdx.x, bh2=blockIdx.z, b=bh2>>3, hk=bh2&7;
    const float* Pk=phik+(LL)bh2*Ss*Ff;
    const float* V=v+(LL)b*Ss*(HKV*DH)+hk*DH;
    __shared__ float As[16][128]; __shared__ float Bs[16][128];
    const int tid=threadIdx.x, tc=tid&15, tr=tid>>4, lr=tid>>5, lc=(tid&31)<<2;
    float acc[8][8];
    #pragma unroll
    for(int i=0;i<8;i++)
        #pragma unroll
        for(int j=0;j<8;j++) acc[i][j]=0.f;
    for(int ks=0;ks<8;ks++){
        int s0=split*128+ks*16;
        #pragma unroll
        for(int pp=0;pp<2;pp++){int r=lr+pp*8;
            *(float4*)&As[r][lc]=*(const float4*)&Pk[(LL)(s0+r)*Ff+lc];
            *(float4*)&Bs[r][lc]=*(const float4*)&V[(LL)(s0+r)*(HKV*DH)+lc];}
        __syncthreads();
        #pragma unroll
        for(int kk=0;kk<16;kk++){
            float ar[8],br[8];
            *(float4*)&ar[0]=*(const float4*)&As[kk][tr*8]; *(float4*)&ar[4]=*(const float4*)&As[kk][tr*8+4];
            *(float4*)&br[0]=*(const float4*)&Bs[kk][tc*8]; *(float4*)&br[4]=*(const float4*)&Bs[kk][tc*8+4];
            #pragma unroll
            for(int i=0;i<8;i++)
                #pragma unroll
                for(int j=0;j<8;j++) acc[i][j]+=ar[i]*br[j];
        }
        __syncthreads();
    }
    float* o=kvpart+((LL)bh2*32+split)*(Ff*DH);
    #pragma unroll
    for(int i=0;i<8;i++)
        #pragma unroll
        for(int j=0;j<8;j++) o[(tr*8+i)*DH+tc*8+j]=acc[i][j];
}
__global__ void z_split(const float* __restrict__ phik, float* __restrict__ zp){
    const int split=blockIdx.x, bh2=blockIdx.y, f=threadIdx.x;
    const float* P=phik+(LL)bh2*Ss*Ff; float s=0.f;
    for(int i=0;i<128;i++) s+=P[(LL)(split*128+i)*Ff+f];
    zp[((LL)bh2*32+split)*Ff+f]=s;
}
__global__ void kv_reduce(const float* __restrict__ kvp, __half* __restrict__ kvh, __half* __restrict__ kvl){
    const int bh=blockIdx.y, bh2=(bh>>4)*8+((bh&15)>>1);
    const int idx=blockIdx.x*128+threadIdx.x;
    const float* p=kvp+(LL)bh2*32*(Ff*DH)+idx;
    float s=0.f;
    #pragma unroll
    for(int sp=0;sp<32;sp++) s+=p[(LL)sp*(Ff*DH)];
    int f=idx>>7, d=idx&127;
    LL o=(LL)bh*(DH*Ff)+(LL)d*Ff+f;
    split2(s,&kvh[o],&kvl[o]);
}
__global__ void z_reduce(const float* __restrict__ zp, float* __restrict__ z){
    const int bh2=blockIdx.x, f=threadIdx.x; float s=0.f;
    #pragma unroll
    for(int sp=0;sp<32;sp++) s+=zp[((LL)bh2*32+sp)*Ff+f];
    z[bh2*Ff+f]=s;
}
__global__ __launch_bounds__(128) void divide_k(const __half* __restrict__ pqh, const __half* __restrict__ pql,
    const float* __restrict__ z, const float* __restrict__ num, __half* __restrict__ ah){
    const int chunk=blockIdx.x, bh=blockIdx.y, tid=threadIdx.x;
    const int b=bh>>4, h=bh&15, bh2=b*8+(h>>1);
    __shared__ float zs[128]; __shared__ float red[4];
    zs[tid]=z[bh2*Ff+tid]; __syncthreads();
    for(int i=0;i<32;i++){
        int s=chunk*32+i;
        LL off=((LL)bh*Ss+s)*Ff+tid;
        float pq=__half2float(pqh[off])+__half2float(pql[off]);
        float pv=pq*zs[tid];
        #pragma unroll
        for(int o=16;o>0;o>>=1) pv+=__shfl_down_sync(0xffffffffu,pv,o);
        if((tid&31)==0) red[tid>>5]=pv;
        __syncthreads();
        float den=red[0]+red[1]+red[2]+red[3];
        float a=num[off]/(den+1e-6f);
        ah[((LL)(b*Ss+s))*Dm+h*DH+tid]=__float2half_rn(a);
        __syncthreads();
    }
}
template<bool HILO>
__global__ __launch_bounds__(256) void ln_k(const float* __restrict__ in, const float* __restrict__ g, const float* __restrict__ be,
    float* __restrict__ out, __half* __restrict__ oh){
    const int row=blockIdx.x, tid=threadIdx.x;
    const float* p=in+(LL)row*Dm;
    float4 a=*(const float4*)&p[tid*4], b4=*(const float4*)&p[1024+tid*4];
    float s=a.x+a.y+a.z+a.w+b4.x+b4.y+b4.z+b4.w;
    float q=a.x*a.x+a.y*a.y+a.z*a.z+a.w*a.w+b4.x*b4.x+b4.y*b4.y+b4.z*b4.z+b4.w*b4.w;
    __shared__ float rs[8], rq[8];
    #pragma unroll
    for(int o=16;o>0;o>>=1){s+=__shfl_down_sync(0xffffffffu,s,o);q+=__shfl_down_sync(0xffffffffu,q,o);}
    if((tid&31)==0){rs[tid>>5]=s;rq[tid>>5]=q;}
    __syncthreads();
    float S=0.f,Q=0.f;
    #pragma unroll
    for(int w=0;w<8;w++){S+=rs[w];Q+=rq[w];}
    float mu=S/(float)Dm, var=Q/(float)Dm-mu*mu, rstd=rsqrtf(var+1e-5f);
    float* po=out+(LL)row*Dm;
    #pragma unroll
    for(int hf=0;hf<2;hf++){
        int c0=hf*1024+tid*4;
        float4 vv=hf?b4:a;
        float4 g4=*(const float4*)&g[c0], bt=*(const float4*)&be[c0];
        float4 o4;
        o4.x=(vv.x-mu)*rstd*g4.x+bt.x; o4.y=(vv.y-mu)*rstd*g4.y+bt.y;
        o4.z=(vv.z-mu)*rstd*g4.z+bt.z; o4.w=(vv.w-mu)*rstd*g4.w+bt.w;
        *(float4*)&po[c0]=o4;
        if(HILO){LL ix=(LL)row*Dm+c0;
            *(__half2*)&oh[ix]  =__halves2half2(__float2half_rn(o4.x),__float2half_rn(o4.y));
            *(__half2*)&oh[ix+2]=__halves2half2(__float2half_rn(o4.z),__float2half_rn(o4.w));}
    }
}

static inline int ssz(int BN,int PH,int ST){
    int nb=(PH>=2)?2:1, na=(PH==3)?2:1;
    return ST*(na*16384 + nb*BN*128);
}

extern "C" void kernel_launch(void* const* d_in, const int* in_sizes, int n_in, void* d_out, int out_size)
{
    const float* x=(const float*)d_in[0];
    const float* W_dq=(const float*)d_in[1];
    const float* W_uq=(const float*)d_in[2];
    const float* W_dkv=(const float*)d_in[3];
    const float* W_uk=(const float*)d_in[4];
    const float* W_uv=(const float*)d_in[5];
    const float* omega=(const float*)d_in[6];
    const float* W_o=(const float*)d_in[7];
    const float* ln1g=(const float*)d_in[8];
    const float* ln1b=(const float*)d_in[9];
    const float* gW=(const float*)d_in[10];
    const float* uW=(const float*)d_in[11];
    const float* dW=(const float*)d_in[12];
    const float* ln2g=(const float*)d_in[13];
    const float* ln2b=(const float*)d_in[14];
    float* out=(float*)d_out;

    #define GA(T,p,s) T* p; cudaGetSymbolAddress((void**)&p, s)
    GA(__half,xh,g_xh); GA(__half,xl,g_xl);
    GA(__half,cqh,g_cqh); GA(__half,cql,g_cql); GA(__half,ckvh,g_ckvh); GA(__half,ckvl,g_ckvl);
    GA(float,q,g_q); GA(float,kk,g_k); GA(float,vv,g_v);
    GA(__half,pqh,g_phiqh); GA(__half,pql,g_phiql); GA(float,pk,g_phik);
    GA(float,kvp,g_kvpart); GA(float,zp,g_zpart);
    GA(__half,kvh,g_kvTh); GA(__half,kvl,g_kvTl);
    GA(float,z,g_z); GA(float,num,g_num);
    GA(__half,ath,g_attnh);
    GA(float,t1,g_t1); GA(float,hb,g_h);
    GA(__half,hh,g_hh);
    GA(__half,acth,g_acth);
    GA(__half,w1h,g_w1h); GA(__half,w1l,g_w1l); GA(__half,w2h,g_w2h); GA(__half,w2l,g_w2l);
    GA(__half,w3h,g_w3h); GA(__half,w3l,g_w3l); GA(__half,w4h,g_w4h); GA(__half,w4l,g_w4l);
    GA(__half,w5h,g_w5h); GA(__half,w5l,g_w5l);
    GA(__half,w6h,g_w6h); GA(__half,w7h,g_w7h); GA(__half,w8h,g_w8h); GA(__half,w9h,g_w9h);
    #undef GA

    cudaFuncSetAttribute(tgemm<64,3,0,2,3>,  cudaFuncAttributeMaxDynamicSharedMemorySize, ssz(64,3,3));
    cudaFuncSetAttribute(tgemm<128,3,0,1,2>, cudaFuncAttributeMaxDynamicSharedMemorySize, ssz(128,3,2));
    cudaFuncSetAttribute(tgemm<256,1,1,1,2>, cudaFuncAttributeMaxDynamicSharedMemorySize, ssz(256,1,2));
    cudaFuncSetAttribute(tgemm2, cudaFuncAttributeMaxDynamicSharedMemorySize, 98304);

    dim3 cb(32,8);
    convT<true><<<dim3(Rr/32,Dm/32),cb>>>(W_dq,w1h,w1l,Dm,Rr);                  // 0
    convT<true><<<dim3(Rr/32,Dm/32),cb>>>(W_dkv,w2h,w2l,Dm,Rr);                 // 1
    convE<<<(int)(((LL)Mtok*Dm/4+255)/256),256>>>(x,xh,xl,(LL)Mtok*Dm);         // 2
    tgemm<64,3,0,2,3><<<dim3(1,Mtok/128),256,ssz(64,3,3)>>>(xh,xl,w1h,w1l,nullptr,nullptr,cqh,cql,Dm,Rr,0,0,0); // 3
    convT<true><<<dim3(Dm/32,Rr/32),cb>>>(W_uq,w3h,w3l,Rr,Dm);                  // 4
    tgemm<64,3,0,2,3><<<dim3(1,Mtok/128),256,ssz(64,3,3)>>>(xh,xl,w2h,w2l,nullptr,nullptr,ckvh,ckvl,Dm,Rr,0,0,0); // 5 <- ncu
    convT<true><<<dim3(HKV*DH/32,Rr/32),cb>>>(W_uk,w4h,w4l,Rr,HKV*DH);
    convT<true><<<dim3(HKV*DH/32,Rr/32),cb>>>(W_uv,w5h,w5l,Rr,HKV*DH);
    convT<false><<<dim3(Dm/32,Dm/32),cb>>>(W_o,w6h,nullptr,Dm,Dm);
    convT<false><<<dim3(DFF/32,Dm/32),cb>>>(gW,w7h,nullptr,Dm,DFF);
    convT<false><<<dim3(DFF/32,Dm/32),cb>>>(uW,w8h,nullptr,Dm,DFF);
    convT<false><<<dim3(Dm/32,DFF/32),cb>>>(dW,w9h,nullptr,DFF,Dm);

    tgemm<128,3,0,1,2><<<dim3(Dm/128,Mtok/128),256,ssz(128,3,2)>>>(cqh,cql,w3h,w3l,nullptr,q,nullptr,nullptr,Rr,Dm,0,0,0);
    tgemm<128,3,0,1,2><<<dim3(HKV*DH/128,Mtok/128),256,ssz(128,3,2)>>>(ckvh,ckvl,w4h,w4l,nullptr,kk,nullptr,nullptr,Rr,HKV*DH,0,0,0);
    tgemm<128,3,0,1,2><<<dim3(HKV*DH/128,Mtok/128),256,ssz(128,3,2)>>>(ckvh,ckvl,w5h,w5l,nullptr,vv,nullptr,nullptr,Rr,HKV*DH,0,0,0);

    phi_kernel<true><<<dim3(Mtok/16,Hh),256>>>(q,omega,nullptr,pqh,pql,Hh,Dm);
    phi_kernel<false><<<dim3(Mtok/16,HKV),256>>>(kk,omega,pk,nullptr,nullptr,HKV,HKV*DH);

    kv_split<<<dim3(32,1,32),256>>>(pk,vv,kvp);
    z_split<<<dim3(32,32),128>>>(pk,zp);
    kv_reduce<<<dim3(Ff*DH/128,64),128>>>(kvp,kvh,kvl);
    z_reduce<<<32,128>>>(zp,z);

    tgemm<128,3,0,1,2><<<dim3(1,Ss/128,64),256,ssz(128,3,2)>>>(pqh,pql,kvh,kvl,nullptr,num,nullptr,nullptr,Ff,DH,(LL)Ss*Ff,(LL)DH*Ff,(LL)Ss*DH);
    divide_k<<<dim3(Ss/32,64),128>>>(pqh,pql,z,num,ath);

    tgemm<256,1,1,1,2><<<dim3(Dm/256,Mtok/128),256,ssz(256,1,2)>>>(ath,nullptr,w6h,nullptr,x,t1,nullptr,nullptr,Dm,Dm,0,0,0);
    ln_k<true><<<Mtok,256>>>(t1,ln1g,ln1b,hb,hh);

    tgemm2<<<8192,256,98304>>>(hh,w7h,w8h,acth);
    tgemm<256,1,1,1,2><<<dim3(Dm/256,Mtok/128),256,ssz(256,1,2)>>>(acth,nullptr,w9h,nullptr,hb,t1,nullptr,nullptr,DFF,Dm,0,0,0);
    ln_k<false><<<Mtok,256>>>(t1,ln2g,ln2b,out,nullptr);
}

// round 13
// speedup vs baseline: 1.7720x; 1.1664x over previous
#include <cuda_runtime.h>
#include <cuda_fp16.h>
#include <cstdint>
#include <math.h>
typedef long long LL;

constexpr int Bb=4, Ss=4096, Dm=2048, DFF=8192, Hh=16, HKV=8, DH=128, Rr=64, KD=64, Ff=128;
constexpr int Mtok=Bb*Ss;

__device__ __forceinline__ uint32_t smem_u32(const void* p){uint32_t a;asm("{ .reg .u64 t; cvta.to.shared.u64 t, %1; cvt.u32.u64 %0, t; }":"=r"(a):"l"(p));return a;}
#define SW128(o) ((o) ^ (((o) >> 3) & 0x70))
#define CPA16(dst,src) asm volatile("cp.async.cg.shared.global [%0], [%1], 16;"::"r"(dst),"l"(src):"memory")
#define CPCOMMIT() asm volatile("cp.async.commit_group;":::"memory")
#define CPWAIT(n) asm volatile("cp.async.wait_group %0;"::"n"(n):"memory")
__device__ __forceinline__ void ldsm4(uint32_t* r, uint32_t a){
    asm volatile("ldmatrix.sync.aligned.m8n8.x4.shared.b16 {%0,%1,%2,%3}, [%4];"
        :"=r"(r[0]),"=r"(r[1]),"=r"(r[2]),"=r"(r[3]):"r"(a));}
#define MMA(d,a,b) asm volatile("mma.sync.aligned.m16n8k16.row.col.f32.f16.f16.f32 {%0,%1,%2,%3},{%4,%5,%6,%7},{%8,%9},{%0,%1,%2,%3};" \
  :"+f"((d)[0]),"+f"((d)[1]),"+f"((d)[2]),"+f"((d)[3]) \
  :"r"((a)[0]),"r"((a)[1]),"r"((a)[2]),"r"((a)[3]),"r"((b)[0]),"r"((b)[1]))

__device__ __align__(16) __half g_xh[(LL)Mtok*Dm];
__device__ __align__(16) __half g_xl[(LL)Mtok*Dm];
__device__ __align__(16) __half g_cqh[(LL)Mtok*Rr];
__device__ __align__(16) __half g_cql[(LL)Mtok*Rr];
__device__ __align__(16) __half g_ckvh[(LL)Mtok*Rr];
__device__ __align__(16) __half g_ckvl[(LL)Mtok*Rr];
__device__ __align__(16) float g_v[(LL)Mtok*HKV*DH];
__device__ __align__(16) __half g_phiqh[(LL)Mtok*Hh*Ff];
__device__ __align__(16) __half g_phiql[(LL)Mtok*Hh*Ff];
__device__ __align__(16) float g_phik[(LL)Mtok*HKV*Ff];
__device__ __align__(16) float g_kvpart[(LL)32*32*Ff*DH];
__device__ __align__(16) float g_zpart[(LL)32*32*Ff];
__device__ __align__(16) __half g_kvTh[(LL)64*DH*Ff];
__device__ __align__(16) __half g_kvTl[(LL)64*DH*Ff];
__device__ __align__(16) float g_z[(LL)32*Ff];
__device__ __align__(16) float g_num[(LL)64*Ss*Ff];
__device__ __align__(16) __half g_attnh[(LL)Mtok*Dm];
__device__ __align__(16) float g_t1[(LL)Mtok*Dm];
__device__ __align__(16) float g_h[(LL)Mtok*Dm];
__device__ __align__(16) __half g_hh[(LL)Mtok*Dm];
__device__ __align__(16) __half g_acth[(LL)Mtok*DFF];
__device__ __align__(16) __half g_w1h[(LL)Rr*Dm];
__device__ __align__(16) __half g_w1l[(LL)Rr*Dm];
__device__ __align__(16) __half g_w2h[(LL)Rr*Dm];
__device__ __align__(16) __half g_w2l[(LL)Rr*Dm];
__device__ __align__(16) __half g_wqomh[(LL)Hh*KD*Rr];
__device__ __align__(16) __half g_wqoml[(LL)Hh*KD*Rr];
__device__ __align__(16) __half g_wkomh[(LL)HKV*KD*Rr];
__device__ __align__(16) __half g_wkoml[(LL)HKV*KD*Rr];
__device__ __align__(16) __half g_w5h[(LL)HKV*DH*Rr];
__device__ __align__(16) __half g_w5l[(LL)HKV*DH*Rr];
__device__ __align__(16) __half g_w6h[(LL)Dm*Dm];
__device__ __align__(16) __half g_w7h[(LL)DFF*Dm];
__device__ __align__(16) __half g_w8h[(LL)DFF*Dm];
__device__ __align__(16) __half g_w9h[(LL)Dm*DFF];

__device__ __forceinline__ void split2(float v, __half* ph, __half* pl){
    __half h=__float2half_rn(v); *ph=h; *pl=__float2half_rn(v-__half2float(h));}

template<bool WRL>
__global__ __launch_bounds__(256) void convT(const float* __restrict__ W, __half* __restrict__ Wh, __half* __restrict__ Wl, int K, int N){
    __shared__ float t[32][33];
    int tx=threadIdx.x, ty=threadIdx.y, k0=blockIdx.y*32, n0=blockIdx.x*32;
    #pragma unroll
    for(int i=0;i<4;i++){int r=ty+i*8; t[r][tx]=W[(LL)(k0+r)*N+n0+tx];}
    __syncthreads();
    #pragma unroll
    for(int i=0;i<4;i++){
        int r=ty+i*8; LL o=(LL)(n0+r)*K+k0+tx; float v=t[tx][r];
        if(WRL) split2(v,&Wh[o],&Wl[o]);
        else Wh[o]=__float2half_rn(v);
    }
}
__global__ __launch_bounds__(256) void convE(const float* __restrict__ X, __half* __restrict__ Xh, __half* __restrict__ Xl, LL n){
    LL i=((LL)blockIdx.x*256+threadIdx.x)*4; if(i>=n) return;
    float4 v=*(const float4*)&X[i];
    split2(v.x,&Xh[i],&Xl[i]); split2(v.y,&Xh[i+1],&Xl[i+1]); split2(v.z,&Xh[i+2],&Xl[i+2]); split2(v.w,&Xh[i+3],&Xl[i+3]);
}
// composed weight: W'[n=h*64+kk][r] = sum_d Wu[r, h*128+d]*omega[d, kk]
__global__ void compose(const float* __restrict__ Wu, const float* __restrict__ omega,
                        __half* __restrict__ Wh, __half* __restrict__ Wl, int nh){
    int n=blockIdx.x, r=threadIdx.x;
    int h=n>>6, kk=n&63;
    float s=0.f;
    for(int d=0;d<DH;d++) s+=Wu[(LL)r*(nh*DH)+h*DH+d]*omega[d*KD+kk];
    LL o=(LL)n*Rr+r;
    split2(s,&Wh[o],&Wl[o]);
}

// C[M,N]=A[M,K]@B[N,K]^T. PH3/PH2/PH1. EPI: 0 none,1 +D,5 phi(sincos). ldc carries nheads for EPI5.
template<int BN,int PH,int EPI,int OUTM,int ST>
__global__ __launch_bounds__(256) void tgemm(
    const __half* __restrict__ Ah, const __half* __restrict__ Al,
    const __half* __restrict__ Bh, const __half* __restrict__ Bl,
    const float* __restrict__ D, float* __restrict__ C,
    __half* __restrict__ Chi, __half* __restrict__ Clo,
    int K, int ldc, LL sA, LL sB, LL sC)
{
    extern __shared__ char smem[];
    const uint32_t sbase=smem_u32(smem);
    const int tid=threadIdx.x, wid=tid>>5, lane=tid&31;
    constexpr int ABYT=16384, BBYT=BN*128, NA=(PH==3)?2:1, NB=(PH>=2)?2:1;
    constexpr int BOFF=NA*ABYT, BUF=BOFF+NB*BBYT;
    const int bm=blockIdx.y*128, bn=blockIdx.x*BN, bz=blockIdx.z;
    const __half* APh=Ah+(LL)bz*sA+(LL)bm*K;
    const __half* APl=(PH==3)?(Al+(LL)bz*sA+(LL)bm*K):nullptr;
    const __half* BPh=Bh+(LL)bz*sB+(LL)bn*K;
    const __half* BPl=(PH>=2)?(Bl+(LL)bz*sB+(LL)bn*K):nullptr;
    const int KT=K>>6;

    auto load=[&](int kt,int buf){
        uint32_t base=sbase+buf*BUF;
        const LL ko=(LL)kt*64;
        #pragma unroll
        for(int i=0;i<4;i++){
            int c=tid+i*256, r=c>>3, ch=c&7; uint32_t sw=SW128(r*128+ch*16);
            CPA16(base+sw, APh+(LL)r*K+ko+ch*8);
            if(PH==3) CPA16(base+ABYT+sw, APl+(LL)r*K+ko+ch*8);
        }
        #pragma unroll
        for(int i=0;i<BN/32;i++){
            int c=tid+i*256, r=c>>3, ch=c&7; uint32_t sw=SW128(r*128+ch*16);
            CPA16(base+BOFF+sw, BPh+(LL)r*K+ko+ch*8);
            if(PH>=2) CPA16(base+BOFF+BBYT+sw, BPl+(LL)r*K+ko+ch*8);
        }
    };

    constexpr int WN=BN/4, NF=WN/8;
    const int g=lane>>2, tg=lane&3, wm=wid&1, wn=wid>>1;
    float acc[4][NF][4];
    #pragma unroll
    for(int i=0;i<4;i++)
        #pragma unroll
        for(int j=0;j<NF;j++){acc[i][j][0]=0.f;acc[i][j][1]=0.f;acc[i][j][2]=0.f;acc[i][j][3]=0.f;}

    const int aquad=lane>>3, alr=lane&7;
    const int arow = wm*64 + ((aquad&1)<<3) + alr;
    const int acol = (aquad>>1)<<4;
    const int brow2 = wn*WN + ((lane>>4)&1)*8 + (lane&7);
    const int bcol  = ((lane>>3)&1)<<4;

    load(0,0); CPCOMMIT();
    if(ST==3 && KT>1){ load(1,1); CPCOMMIT(); }
    for(int kt=0;kt<KT;kt++){
        if(ST==2){
            if(kt+1<KT){ load(kt+1,(kt+1)&1); CPCOMMIT(); CPWAIT(1); }
            else CPWAIT(0);
        } else {
            if(kt+2<KT){ load(kt+2,(kt+2)%3); CPCOMMIT(); CPWAIT(2); }
            else if(kt+1<KT) CPWAIT(1);
            else CPWAIT(0);
        }
        __syncthreads();
        const uint32_t cbase=sbase+(kt%ST)*BUF;
        #pragma unroll
        for(int ks=0;ks<4;ks++){
            uint32_t ahf[4][4], alf[4][4], bhf[NF][2], blf[NF][2];
            #pragma unroll
            for(int mf=0;mf<4;mf++){
                uint32_t ad=cbase+SW128((arow+mf*16)*128 + ks*32+acol);
                ldsm4(ahf[mf], ad);
                if(PH==3) ldsm4(alf[mf], ad+ABYT);
            }
            #pragma unroll
            for(int np=0;np<NF/2;np++){
                uint32_t bd=cbase+BOFF+SW128((brow2+np*16)*128 + ks*32+bcol);
                uint32_t t4[4];
                ldsm4(t4,bd);
                bhf[2*np][0]=t4[0];bhf[2*np][1]=t4[1];bhf[2*np+1][0]=t4[2];bhf[2*np+1][1]=t4[3];
                if(PH>=2){
                    ldsm4(t4,bd+BBYT);
                    blf[2*np][0]=t4[0];blf[2*np][1]=t4[1];blf[2*np+1][0]=t4[2];blf[2*np+1][1]=t4[3];
                }
            }
            #pragma unroll
            for(int mf=0;mf<4;mf++)
                #pragma unroll
                for(int nf=0;nf<NF;nf++){
                    MMA(acc[mf][nf], ahf[mf], bhf[nf]);
                    if(PH>=2) MMA(acc[mf][nf], ahf[mf], blf[nf]);
                    if(PH==3) MMA(acc[mf][nf], alf[mf], bhf[nf]);
                }
        }
        __syncthreads();
    }

    #pragma unroll
    for(int mf=0;mf<4;mf++)
        #pragma unroll
        for(int nf=0;nf<NF;nf++)
            #pragma unroll
            for(int hr=0;hr<2;hr++){
                int r=bm+wm*64+mf*16+g+hr*8;
                int c=bn+wn*WN+nf*8+tg*2;
                float v0=acc[mf][nf][hr*2], v1=acc[mf][nf][hr*2+1];
                if(EPI==5){
                    // phi epilogue: r=token, c=h*64+kk; write cos/sin*0.125
                    const int nh=ldc;
                    int b=r>>12, sr=r&4095;
                    int h=c>>6, kk=c&63;
                    LL base=((LL)(b*nh+h)*Ss+sr)*Ff;
                    float s0,c0,s1,c1;
                    __sincosf(v0,&s0,&c0); __sincosf(v1,&s1,&c1);
                    c0*=0.125f; s0*=0.125f; c1*=0.125f; s1*=0.125f;
                    if(OUTM&1){
                        C[base+kk]=c0; C[base+kk+1]=c1;
                        C[base+KD+kk]=s0; C[base+KD+kk+1]=s1;
                    }
                    if(OUTM&2){
                        __half hc0=__float2half_rn(c0), hc1=__float2half_rn(c1);
                        __half hs0=__float2half_rn(s0), hs1=__float2half_rn(s1);
                        *(__half2*)&Chi[base+kk]=__halves2half2(hc0,hc1);
                        *(__half2*)&Chi[base+KD+kk]=__halves2half2(hs0,hs1);
                        *(__half2*)&Clo[base+kk]=__halves2half2(
                            __float2half_rn(c0-__half2float(hc0)), __float2half_rn(c1-__half2float(hc1)));
                        *(__half2*)&Clo[base+KD+kk]=__halves2half2(
                            __float2half_rn(s0-__half2float(hs0)), __float2half_rn(s1-__half2float(hs1)));
                    }
                    continue;
                }
                LL idx=(LL)bz*sC+(LL)r*ldc+c;
                if(EPI==1){float2 d2=*(const float2*)&D[idx]; v0+=d2.x; v1+=d2.y;}
                if(OUTM&1){float2 o2; o2.x=v0; o2.y=v1; *(float2*)&C[idx]=o2;}
                if(OUTM&2){
                    __half h0=__float2half_rn(v0), h1=__float2half_rn(v1);
                    *(__half2*)&Chi[idx]=__halves2half2(h0,h1);
                    *(__half2*)&Clo[idx]=__halves2half2(
                        __float2half_rn(v0-__half2float(h0)), __float2half_rn(v1-__half2float(h1)));
                }
                if(OUTM&4){
                    *(__half2*)&Chi[idx]=__halves2half2(__float2half_rn(v0),__float2half_rn(v1));
                }
            }
}

// Fused gate+up
__global__ __launch_bounds__(256) void tgemm2(
    const __half* __restrict__ Ah,
    const __half* __restrict__ Bgh, const __half* __restrict__ Buh,
    __half* __restrict__ Co)
{
    extern __shared__ char smem[];
    const uint32_t sbase=smem_u32(smem);
    const int tid=threadIdx.x, wid=tid>>5, lane=tid&31;
    constexpr int ABYT=32768, BBYT=8192, BUF=ABYT+2*BBYT;
    const int idx0=blockIdx.x;
    const int grp=idx0>>10, rem=idx0&1023;
    const int bm=(grp*8+(rem&7))*256, bn=(rem>>3)*64;
    const __half* AP=Ah+(LL)bm*Dm;
    const __half* Bg=Bgh+(LL)bn*Dm;
    const __half* Bu=Buh+(LL)bn*Dm;
    const int KT=Dm>>6;

    auto load=[&](int kt,int buf){
        uint32_t base=sbase+buf*BUF;
        const LL ko=(LL)kt*64;
        #pragma unroll
        for(int i=0;i<8;i++){
            int c=tid+i*256, r=c>>3, ch=c&7; uint32_t sw=SW128(r*128+ch*16);
            CPA16(base+sw, AP+(LL)r*Dm+ko+ch*8);
        }
        #pragma unroll
        for(int i=0;i<2;i++){
            int c=tid+i*256, r=c>>3, ch=c&7; uint32_t sw=SW128(r*128+ch*16);
            CPA16(base+ABYT+sw,      Bg+(LL)r*Dm+ko+ch*8);
            CPA16(base+ABYT+BBYT+sw, Bu+(LL)r*Dm+ko+ch*8);
        }
    };

    const int g=lane>>2, tg=lane&3, wm=wid&3, wn=wid>>2;
    float accg[4][4][4], accu[4][4][4];
    #pragma unroll
    for(int i=0;i<4;i++)
        #pragma unroll
        for(int j=0;j<4;j++)
            #pragma unroll
            for(int e=0;e<4;e++){accg[i][j][e]=0.f;accu[i][j][e]=0.f;}

    const int aquad=lane>>3, alr=lane&7;
    const int arow = wm*64 + ((aquad&1)<<3) + alr;
    const int acol = (aquad>>1)<<4;
    const int brow2 = wn*32 + ((lane>>4)&1)*8 + (lane&7);
    const int bcol  = ((lane>>3)&1)<<4;

    load(0,0); CPCOMMIT();
    for(int kt=0;kt<KT;kt++){
        if(kt+1<KT){ load(kt+1,(kt+1)&1); CPCOMMIT(); CPWAIT(1); }
        else CPWAIT(0);
        __syncthreads();
        const uint32_t cbase=sbase+(kt&1)*BUF;
        #pragma unroll
        for(int ks=0;ks<4;ks++){
            uint32_t ahf[4][4], bgf[4][2], buf_[4][2];
            #pragma unroll
            for(int mf=0;mf<4;mf++)
                ldsm4(ahf[mf], cbase+SW128((arow+mf*16)*128 + ks*32+acol));
            #pragma unroll
            for(int np=0;np<2;np++){
                uint32_t bd=cbase+ABYT+SW128((brow2+np*16)*128 + ks*32+bcol);
                uint32_t t4[4];
                ldsm4(t4,bd);      bgf[2*np][0]=t4[0];bgf[2*np][1]=t4[1];bgf[2*np+1][0]=t4[2];bgf[2*np+1][1]=t4[3];
                ldsm4(t4,bd+BBYT); buf_[2*np][0]=t4[0];buf_[2*np][1]=t4[1];buf_[2*np+1][0]=t4[2];buf_[2*np+1][1]=t4[3];
            }
            #pragma unroll
            for(int mf=0;mf<4;mf++)
                #pragma unroll
                for(int nf=0;nf<4;nf++){
                    MMA(accg[mf][nf], ahf[mf], bgf[nf]);
                    MMA(accu[mf][nf], ahf[mf], buf_[nf]);
                }
        }
        __syncthreads();
    }

    #pragma unroll
    for(int mf=0;mf<4;mf++)
        #pragma unroll
        for(int nf=0;nf<4;nf++)
            #pragma unroll
            for(int hr=0;hr<2;hr++){
                int r=bm+wm*64+mf*16+g+hr*8;
                int c=bn+wn*32+nf*8+tg*2;
                LL idx=(LL)r*DFF+c;
                float g0=accg[mf][nf][hr*2], g1=accg[mf][nf][hr*2+1];
                float u0=accu[mf][nf][hr*2], u1=accu[mf][nf][hr*2+1];
                float a0=g0*(u0/(1.f+expf(-u0))), a1=g1*(u1/(1.f+expf(-u1)));
                *(__half2*)&Co[idx]=__halves2half2(__float2half_rn(a0),__float2half_rn(a1));
            }
}

__global__ __launch_bounds__(256) void kv_split(const float* __restrict__ phik, const float* __restrict__ v, float* __restrict__ kvpart){
    const int split=blockIdx.x, bh2=blockIdx.z, b=bh2>>3, hk=bh2&7;
    const float* Pk=phik+(LL)bh2*Ss*Ff;
    const float* V=v+(LL)b*Ss*(HKV*DH)+hk*DH;
    __shared__ float As[16][128]; __shared__ float Bs[16][128];
    const int tid=threadIdx.x, tc=tid&15, tr=tid>>4, lr=tid>>5, lc=(tid&31)<<2;
    float acc[8][8];
    #pragma unroll
    for(int i=0;i<8;i++)
        #pragma unroll
        for(int j=0;j<8;j++) acc[i][j]=0.f;
    for(int ks=0;ks<8;ks++){
        int s0=split*128+ks*16;
        #pragma unroll
        for(int pp=0;pp<2;pp++){int r=lr+pp*8;
            *(float4*)&As[r][lc]=*(const float4*)&Pk[(LL)(s0+r)*Ff+lc];
            *(float4*)&Bs[r][lc]=*(const float4*)&V[(LL)(s0+r)*(HKV*DH)+lc];}
        __syncthreads();
        #pragma unroll
        for(int kk=0;kk<16;kk++){
            float ar[8],br[8];
            *(float4*)&ar[0]=*(const float4*)&As[kk][tr*8]; *(float4*)&ar[4]=*(const float4*)&As[kk][tr*8+4];
            *(float4*)&br[0]=*(const float4*)&Bs[kk][tc*8]; *(float4*)&br[4]=*(const float4*)&Bs[kk][tc*8+4];
            #pragma unroll
            for(int i=0;i<8;i++)
                #pragma unroll
                for(int j=0;j<8;j++) acc[i][j]+=ar[i]*br[j];
        }
        __syncthreads();
    }
    float* o=kvpart+((LL)bh2*32+split)*(Ff*DH);
    #pragma unroll
    for(int i=0;i<8;i++)
        #pragma unroll
        for(int j=0;j<8;j++) o[(tr*8+i)*DH+tc*8+j]=acc[i][j];
}
__global__ void z_split(const float* __restrict__ phik, float* __restrict__ zp){
    const int split=blockIdx.x, bh2=blockIdx.y, f=threadIdx.x;
    const float* P=phik+(LL)bh2*Ss*Ff; float s=0.f;
    for(int i=0;i<128;i++) s+=P[(LL)(split*128+i)*Ff+f];
    zp[((LL)bh2*32+split)*Ff+f]=s;
}
__global__ void kv_reduce(const float* __restrict__ kvp, __half* __restrict__ kvh, __half* __restrict__ kvl){
    const int bh=blockIdx.y, bh2=(bh>>4)*8+((bh&15)>>1);
    const int idx=blockIdx.x*128+threadIdx.x;
    const float* p=kvp+(LL)bh2*32*(Ff*DH)+idx;
    float s=0.f;
    #pragma unroll
    for(int sp=0;sp<32;sp++) s+=p[(LL)sp*(Ff*DH)];
    int f=idx>>7, d=idx&127;
    LL o=(LL)bh*(DH*Ff)+(LL)d*Ff+f;
    split2(s,&kvh[o],&kvl[o]);
}
__global__ void z_reduce(const float* __restrict__ zp, float* __restrict__ z){
    const int bh2=blockIdx.x, f=threadIdx.x; float s=0.f;
    #pragma unroll
    for(int sp=0;sp<32;sp++) s+=zp[((LL)bh2*32+sp)*Ff+f];
    z[bh2*Ff+f]=s;
}
__global__ __launch_bounds__(128) void divide_k(const __half* __restrict__ pqh, const __half* __restrict__ pql,
    const float* __restrict__ z, const float* __restrict__ num, __half* __restrict__ ah){
    const int chunk=blockIdx.x, bh=blockIdx.y, tid=threadIdx.x;
    const int b=bh>>4, h=bh&15, bh2=b*8+(h>>1);
    __shared__ float zs[128]; __shared__ float red[4];
    zs[tid]=z[bh2*Ff+tid]; __syncthreads();
    for(int i=0;i<32;i++){
        int s=chunk*32+i;
        LL off=((LL)bh*Ss+s)*Ff+tid;
        float pq=__half2float(pqh[off])+__half2float(pql[off]);
        float pv=pq*zs[tid];
        #pragma unroll
        for(int o=16;o>0;o>>=1) pv+=__shfl_down_sync(0xffffffffu,pv,o);
        if((tid&31)==0) red[tid>>5]=pv;
        __syncthreads();
        float den=red[0]+red[1]+red[2]+red[3];
        float a=num[off]/(den+1e-6f);
        ah[((LL)(b*Ss+s))*Dm+h*DH+tid]=__float2half_rn(a);
        __syncthreads();
    }
}
template<bool HILO>
__global__ __launch_bounds__(256) void ln_k(const float* __restrict__ in, const float* __restrict__ g, const float* __restrict__ be,
    float* __restrict__ out, __half* __restrict__ oh){
    const int row=blockIdx.x, tid=threadIdx.x;
    const float* p=in+(LL)row*Dm;
    float4 a=*(const float4*)&p[tid*4], b4=*(const float4*)&p[1024+tid*4];
    float s=a.x+a.y+a.z+a.w+b4.x+b4.y+b4.z+b4.w;
    float q=a.x*a.x+a.y*a.y+a.z*a.z+a.w*a.w+b4.x*b4.x+b4.y*b4.y+b4.z*b4.z+b4.w*b4.w;
    __shared__ float rs[8], rq[8];
    #pragma unroll
    for(int o=16;o>0;o>>=1){s+=__shfl_down_sync(0xffffffffu,s,o);q+=__shfl_down_sync(0xffffffffu,q,o);}
    if((tid&31)==0){rs[tid>>5]=s;rq[tid>>5]=q;}
    __syncthreads();
    float S=0.f,Q=0.f;
    #pragma unroll
    for(int w=0;w<8;w++){S+=rs[w];Q+=rq[w];}
    float mu=S/(float)Dm, var=Q/(float)Dm-mu*mu, rstd=rsqrtf(var+1e-5f);
    float* po=out+(LL)row*Dm;
    #pragma unroll
    for(int hf=0;hf<2;hf++){
        int c0=hf*1024+tid*4;
        float4 vv=hf?b4:a;
        float4 g4=*(const float4*)&g[c0], bt=*(const float4*)&be[c0];
        float4 o4;
        o4.x=(vv.x-mu)*rstd*g4.x+bt.x; o4.y=(vv.y-mu)*rstd*g4.y+bt.y;
        o4.z=(vv.z-mu)*rstd*g4.z+bt.z; o4.w=(vv.w-mu)*rstd*g4.w+bt.w;
        *(float4*)&po[c0]=o4;
        if(HILO){LL ix=(LL)row*Dm+c0;
            *(__half2*)&oh[ix]  =__halves2half2(__float2half_rn(o4.x),__float2half_rn(o4.y));
            *(__half2*)&oh[ix+2]=__halves2half2(__float2half_rn(o4.z),__float2half_rn(o4.w));}
    }
}

static inline int ssz(int BN,int PH,int ST){
    int nb=(PH>=2)?2:1, na=(PH==3)?2:1;
    return ST*(na*16384 + nb*BN*128);
}

extern "C" void kernel_launch(void* const* d_in, const int* in_sizes, int n_in, void* d_out, int out_size)
{
    const float* x=(const float*)d_in[0];
    const float* W_dq=(const float*)d_in[1];
    const float* W_uq=(const float*)d_in[2];
    const float* W_dkv=(const float*)d_in[3];
    const float* W_uk=(const float*)d_in[4];
    const float* W_uv=(const float*)d_in[5];
    const float* omega=(const float*)d_in[6];
    const float* W_o=(const float*)d_in[7];
    const float* ln1g=(const float*)d_in[8];
    const float* ln1b=(const float*)d_in[9];
    const float* gW=(const float*)d_in[10];
    const float* uW=(const float*)d_in[11];
    const float* dW=(const float*)d_in[12];
    const float* ln2g=(const float*)d_in[13];
    const float* ln2b=(const float*)d_in[14];
    float* out=(float*)d_out;

    #define GA(T,p,s) T* p; cudaGetSymbolAddress((void**)&p, s)
    GA(__half,xh,g_xh); GA(__half,xl,g_xl);
    GA(__half,cqh,g_cqh); GA(__half,cql,g_cql); GA(__half,ckvh,g_ckvh); GA(__half,ckvl,g_ckvl);
    GA(float,vv,g_v);
    GA(__half,pqh,g_phiqh); GA(__half,pql,g_phiql); GA(float,pk,g_phik);
    GA(float,kvp,g_kvpart); GA(float,zp,g_zpart);
    GA(__half,kvh,g_kvTh); GA(__half,kvl,g_kvTl);
    GA(float,z,g_z); GA(float,num,g_num);
    GA(__half,ath,g_attnh);
    GA(float,t1,g_t1); GA(float,hb,g_h);
    GA(__half,hh,g_hh);
    GA(__half,acth,g_acth);
    GA(__half,w1h,g_w1h); GA(__half,w1l,g_w1l); GA(__half,w2h,g_w2h); GA(__half,w2l,g_w2l);
    GA(__half,wqomh,g_wqomh); GA(__half,wqoml,g_wqoml);
    GA(__half,wkomh,g_wkomh); GA(__half,wkoml,g_wkoml);
    GA(__half,w5h,g_w5h); GA(__half,w5l,g_w5l);
    GA(__half,w6h,g_w6h); GA(__half,w7h,g_w7h); GA(__half,w8h,g_w8h); GA(__half,w9h,g_w9h);
    #undef GA

    cudaFuncSetAttribute(tgemm<64,3,0,2,3>,  cudaFuncAttributeMaxDynamicSharedMemorySize, ssz(64,3,3));
    cudaFuncSetAttribute(tgemm<128,3,0,1,2>, cudaFuncAttributeMaxDynamicSharedMemorySize, ssz(128,3,2));
    cudaFuncSetAttribute(tgemm<128,3,5,2,2>, cudaFuncAttributeMaxDynamicSharedMemorySize, ssz(128,3,2));
    cudaFuncSetAttribute(tgemm<128,3,5,1,2>, cudaFuncAttributeMaxDynamicSharedMemorySize, ssz(128,3,2));
    cudaFuncSetAttribute(tgemm<256,1,1,1,2>, cudaFuncAttributeMaxDynamicSharedMemorySize, ssz(256,1,2));
    cudaFuncSetAttribute(tgemm2, cudaFuncAttributeMaxDynamicSharedMemorySize, 98304);

    dim3 cb(32,8);
    convT<true><<<dim3(Rr/32,Dm/32),cb>>>(W_dq,w1h,w1l,Dm,Rr);                  // 0
    convT<true><<<dim3(Rr/32,Dm/32),cb>>>(W_dkv,w2h,w2l,Dm,Rr);                 // 1
    convE<<<(int)(((LL)Mtok*Dm/4+255)/256),256>>>(x,xh,xl,(LL)Mtok*Dm);         // 2
    tgemm<64,3,0,2,3><<<dim3(1,Mtok/128),256,ssz(64,3,3)>>>(xh,xl,w1h,w1l,nullptr,nullptr,cqh,cql,Dm,Rr,0,0,0); // 3
    compose<<<Hh*KD,Rr>>>(W_uq,omega,wqomh,wqoml,Hh);                           // 4
    tgemm<64,3,0,2,3><<<dim3(1,Mtok/128),256,ssz(64,3,3)>>>(xh,xl,w2h,w2l,nullptr,nullptr,ckvh,ckvl,Dm,Rr,0,0,0); // 5 <- ncu
    compose<<<HKV*KD,Rr>>>(W_uk,omega,wkomh,wkoml,HKV);
    convT<true><<<dim3(HKV*DH/32,Rr/32),cb>>>(W_uv,w5h,w5l,Rr,HKV*DH);
    convT<false><<<dim3(Dm/32,Dm/32),cb>>>(W_o,w6h,nullptr,Dm,Dm);
    convT<false><<<dim3(DFF/32,Dm/32),cb>>>(gW,w7h,nullptr,Dm,DFF);
    convT<false><<<dim3(DFF/32,Dm/32),cb>>>(uW,w8h,nullptr,Dm,DFF);
    convT<false><<<dim3(Dm/32,DFF/32),cb>>>(dW,w9h,nullptr,DFF,Dm);

    // phi_q / phi_k directly from latents via composed weights (EPI=5)
    tgemm<128,3,5,2,2><<<dim3(Hh*KD/128,Mtok/128),256,ssz(128,3,2)>>>(cqh,cql,wqomh,wqoml,nullptr,nullptr,pqh,pql,Rr,Hh,0,0,0);
    tgemm<128,3,5,1,2><<<dim3(HKV*KD/128,Mtok/128),256,ssz(128,3,2)>>>(ckvh,ckvl,wkomh,wkoml,nullptr,pk,nullptr,nullptr,Rr,HKV,0,0,0);
    // v
    tgemm<128,3,0,1,2><<<dim3(HKV*DH/128,Mtok/128),256,ssz(128,3,2)>>>(ckvh,ckvl,w5h,w5l,nullptr,vv,nullptr,nullptr,Rr,HKV*DH,0,0,0);

    kv_split<<<dim3(32,1,32),256>>>(pk,vv,kvp);
    z_split<<<dim3(32,32),128>>>(pk,zp);
    kv_reduce<<<dim3(Ff*DH/128,64),128>>>(kvp,kvh,kvl);
    z_reduce<<<32,128>>>(zp,z);

    tgemm<128,3,0,1,2><<<dim3(1,Ss/128,64),256,ssz(128,3,2)>>>(pqh,pql,kvh,kvl,nullptr,num,nullptr,nullptr,Ff,DH,(LL)Ss*Ff,(LL)DH*Ff,(LL)Ss*DH);
    divide_k<<<dim3(Ss/32,64),128>>>(pqh,pql,z,num,ath);

    tgemm<256,1,1,1,2><<<dim3(Dm/256,Mtok/128),256,ssz(256,1,2)>>>(ath,nullptr,w6h,nullptr,x,t1,nullptr,nullptr,Dm,Dm,0,0,0);
    ln_k<true><<<Mtok,256>>>(t1,ln1g,ln1b,hb,hh);

    tgemm2<<<8192,256,98304>>>(hh,w7h,w8h,acth);
    tgemm<256,1,1,1,2><<<dim3(Dm/256,Mtok/128),256,ssz(256,1,2)>>>(acth,nullptr,w9h,nullptr,hb,t1,nullptr,nullptr,DFF,Dm,0,0,0);
    ln_k<false><<<Mtok,256>>>(t1,ln2g,ln2b,out,nullptr);
}